// round 3
// baseline (speedup 1.0000x reference)
#include <cuda_runtime.h>
#include <cuda_bf16.h>

#define N_NODES 50000
#define DIM     128
#define N_EDGES 800000
#define BM      64

// Scratch (device globals — no allocation allowed in kernel_launch)
__device__ float g_deg [2 * N_NODES];
__device__ float g_dinv[2 * N_NODES];
__device__ float g_hs  [N_NODES * DIM];
__device__ float g_acc [N_NODES * DIM];
__device__ float g_h   [N_NODES * DIM];

// ---------------------------------------------------------------------------
// Degree: deg = 1 (self loop) + indegree; dinv = rsqrt(deg)
// ---------------------------------------------------------------------------
__global__ void k_init_deg() {
    int i = blockIdx.x * blockDim.x + threadIdx.x;
    if (i < 2 * N_NODES) g_deg[i] = 1.0f;
}

__global__ void k_count_deg(const int* __restrict__ dst, float* __restrict__ deg) {
    int e = blockIdx.x * blockDim.x + threadIdx.x;
    int stride = gridDim.x * blockDim.x;
    for (; e < N_EDGES; e += stride)
        atomicAdd(&deg[__ldg(dst + e)], 1.0f);
}

__global__ void k_dinv() {
    int i = blockIdx.x * blockDim.x + threadIdx.x;
    if (i < 2 * N_NODES) g_dinv[i] = rsqrtf(g_deg[i]);
}

// ---------------------------------------------------------------------------
// GEMM: hs[m][:] = (x[m][:] @ W) * dinv[m]; also zeroes acc rows for this tile
// Block tile 64(M) x 128(N), full K=128 split in two 64-chunks.
// smem: W chunk 64x128 (32KB) + x chunk 64x64 (16KB) = 48KB static.
// ---------------------------------------------------------------------------
__global__ __launch_bounds__(256)
void k_gemm_scale(const float* __restrict__ x, const float* __restrict__ W,
                  const float* __restrict__ dinv,
                  float* __restrict__ hs, float* __restrict__ acc) {
    __shared__ float Wsh[64 * 128];
    __shared__ float xsh[64 * 64];

    const int tid = threadIdx.x;
    const int ty = tid >> 4;     // 0..15 -> 4 rows each
    const int tx = tid & 15;     // 0..15 -> 8 cols each
    const int row0 = blockIdx.x * BM;

    float a[4][8];
#pragma unroll
    for (int i = 0; i < 4; i++)
#pragma unroll
        for (int j = 0; j < 8; j++) a[i][j] = 0.0f;

    for (int kt = 0; kt < 2; kt++) {
        // Load W[kt*64 .. +63][0..127]: 2048 float4, 8 per thread
        const float4* Wg = (const float4*)(W + kt * 64 * 128);
        float4* Ws4 = (float4*)Wsh;
#pragma unroll
        for (int r = 0; r < 8; r++)
            Ws4[tid + r * 256] = Wg[tid + r * 256];

        // Load x rows [row0, row0+64), cols [kt*64, kt*64+64): 1024 float4, 4/thread
        float4* xs4 = (float4*)xsh;
#pragma unroll
        for (int r = 0; r < 4; r++) {
            int f = tid + r * 256;
            int rr = f >> 4;          // row within tile
            int c4 = f & 15;          // float4 within 64-col chunk
            int grow = row0 + rr;
            float4 v = make_float4(0.f, 0.f, 0.f, 0.f);
            if (grow < N_NODES)
                v = ((const float4*)(x + (size_t)grow * DIM + kt * 64))[c4];
            xs4[f] = v;
        }
        __syncthreads();

#pragma unroll 8
        for (int k = 0; k < 64; k++) {
            float xv[4];
#pragma unroll
            for (int i = 0; i < 4; i++) xv[i] = xsh[(ty * 4 + i) * 64 + k];
            float4 w0 = ((const float4*)Wsh)[k * 32 + tx * 2];
            float4 w1 = ((const float4*)Wsh)[k * 32 + tx * 2 + 1];
            float wv[8] = {w0.x, w0.y, w0.z, w0.w, w1.x, w1.y, w1.z, w1.w};
#pragma unroll
            for (int i = 0; i < 4; i++)
#pragma unroll
                for (int j = 0; j < 8; j++)
                    a[i][j] = fmaf(xv[i], wv[j], a[i][j]);
        }
        __syncthreads();
    }

    // Epilogue: hs = a * dinv[row]; acc = 0
#pragma unroll
    for (int i = 0; i < 4; i++) {
        int row = row0 + ty * 4 + i;
        if (row >= N_NODES) continue;
        float d = __ldg(dinv + row);
        float4 o0 = make_float4(a[i][0] * d, a[i][1] * d, a[i][2] * d, a[i][3] * d);
        float4 o1 = make_float4(a[i][4] * d, a[i][5] * d, a[i][6] * d, a[i][7] * d);
        float4* hrow = (float4*)(hs + (size_t)row * DIM);
        float4* arow = (float4*)(acc + (size_t)row * DIM);
        hrow[tx * 2]     = o0;
        hrow[tx * 2 + 1] = o1;
        float4 z = make_float4(0.f, 0.f, 0.f, 0.f);
        arow[tx * 2]     = z;
        arow[tx * 2 + 1] = z;
    }
}

// ---------------------------------------------------------------------------
// Scatter: one warp per edge; lane l handles float4 chunk l of the 128-dim row.
// acc[dst] += hs[src]  (float4 L2 atomics, sm_90+)
// ---------------------------------------------------------------------------
__global__ __launch_bounds__(256)
void k_scatter(const int* __restrict__ src, const int* __restrict__ dst,
               const float* __restrict__ hs, float* __restrict__ acc) {
    int warp  = (blockIdx.x * blockDim.x + threadIdx.x) >> 5;
    int lane  = threadIdx.x & 31;
    int nwarp = (gridDim.x * blockDim.x) >> 5;
    const float4* hs4 = (const float4*)hs;
    float4* acc4 = (float4*)acc;
    for (int e = warp; e < N_EDGES; e += nwarp) {
        int s = __ldg(src + e);
        int d = __ldg(dst + e);
        float4 v = __ldg(hs4 + (size_t)s * 32 + lane);
        atomicAdd(acc4 + (size_t)d * 32 + lane, v);
    }
}

// ---------------------------------------------------------------------------
// Finalize: out = (acc + hs) * dinv + b, optional ReLU
// ---------------------------------------------------------------------------
__global__ __launch_bounds__(256)
void k_finalize(const float* __restrict__ acc, const float* __restrict__ hs,
                const float* __restrict__ dinv, const float* __restrict__ b,
                float* __restrict__ out, int do_relu) {
    int i = blockIdx.x * blockDim.x + threadIdx.x;   // over N_NODES*32 float4s
    if (i >= N_NODES * 32) return;
    int row = i >> 5;
    int c4  = i & 31;
    float4 a = ((const float4*)acc)[i];
    float4 h = ((const float4*)hs)[i];
    float  d = __ldg(dinv + row);
    float4 bb = ((const float4*)b)[c4];
    float4 o;
    o.x = fmaf(a.x + h.x, d, bb.x);
    o.y = fmaf(a.y + h.y, d, bb.y);
    o.z = fmaf(a.z + h.z, d, bb.z);
    o.w = fmaf(a.w + h.w, d, bb.w);
    if (do_relu) {
        o.x = fmaxf(o.x, 0.f); o.y = fmaxf(o.y, 0.f);
        o.z = fmaxf(o.z, 0.f); o.w = fmaxf(o.w, 0.f);
    }
    ((float4*)out)[i] = o;
}

// ---------------------------------------------------------------------------
// Launch
// ---------------------------------------------------------------------------
static void run_layer(const float* x, const int* esrc, const int* edst,
                      const float* W, const float* b, const float* dinv,
                      float* hs, float* acc, float* out, int do_relu) {
    k_gemm_scale<<<(N_NODES + BM - 1) / BM, 256>>>(x, W, dinv, hs, acc);
    k_scatter<<<2048, 256>>>(esrc, edst, hs, acc);
    k_finalize<<<(N_NODES * 32 + 255) / 256, 256>>>(acc, hs, dinv, b, out, do_relu);
}

extern "C" void kernel_launch(void* const* d_in, const int* in_sizes, int n_in,
                              void* d_out, int out_size) {
    const float* x1  = (const float*)d_in[0];
    const int*   ei1 = (const int*)  d_in[1];
    const float* x2  = (const float*)d_in[2];
    const int*   ei2 = (const int*)  d_in[3];
    const float* W0  = (const float*)d_in[4];
    const float* b0  = (const float*)d_in[5];
    const float* W1  = (const float*)d_in[6];
    const float* b1  = (const float*)d_in[7];
    float* out = (float*)d_out;

    const int* src1 = ei1;
    const int* dst1 = ei1 + N_EDGES;
    const int* src2 = ei2;
    const int* dst2 = ei2 + N_EDGES;

    float *deg, *dinv, *hs, *acc, *h;
    cudaGetSymbolAddress((void**)&deg,  g_deg);
    cudaGetSymbolAddress((void**)&dinv, g_dinv);
    cudaGetSymbolAddress((void**)&hs,   g_hs);
    cudaGetSymbolAddress((void**)&acc,  g_acc);
    cudaGetSymbolAddress((void**)&h,    g_h);

    // Degrees / normalization for both graphs
    k_init_deg<<<(2 * N_NODES + 255) / 256, 256>>>();
    k_count_deg<<<1024, 256>>>(dst1, deg);
    k_count_deg<<<1024, 256>>>(dst2, deg + N_NODES);
    k_dinv<<<(2 * N_NODES + 255) / 256, 256>>>();

    // Graph 1
    run_layer(x1, src1, dst1, W0, b0, dinv,            hs, acc, h,   1);
    run_layer(h,  src1, dst1, W1, b1, dinv,            hs, acc, out, 0);
    // Graph 2
    run_layer(x2, src2, dst2, W0, b0, dinv + N_NODES,  hs, acc, h,   1);
    run_layer(h,  src2, dst2, W1, b1, dinv + N_NODES,  hs, acc, out + (size_t)N_NODES * DIM, 0);
}

// round 4
// speedup vs baseline: 1.3066x; 1.3066x over previous
#include <cuda_runtime.h>
#include <cuda_bf16.h>

#define N_NODES 50000
#define DIM     128
#define N_EDGES 800000
#define BM      64

// ---------------------------------------------------------------------------
// Scratch (device globals — no allocation allowed in kernel_launch)
// ---------------------------------------------------------------------------
__device__ int   g_cnt [2 * N_NODES];          // in-degree counts (per graph)
__device__ int   g_offs[2 * (N_NODES + 1)];    // CSR row offsets (per graph)
__device__ int   g_cur [2 * N_NODES];          // fill cursors
__device__ int   g_csr [2 * N_EDGES];          // src indices bucketed by dst
__device__ float g_dinv[2 * N_NODES];
__device__ float g_hs  [N_NODES * DIM];        // (x @ W) * dinv[row]
__device__ float g_h   [N_NODES * DIM];        // hidden layer activations

// ---------------------------------------------------------------------------
// CSR build: zero counts -> count -> scan -> (dinv + cursor) -> fill
// ---------------------------------------------------------------------------
__global__ void k_zero_cnt() {
    int i = blockIdx.x * blockDim.x + threadIdx.x;
    if (i < 2 * N_NODES) g_cnt[i] = 0;
}

__global__ void k_count(const int* __restrict__ dst, int* __restrict__ cnt) {
    int e = blockIdx.x * blockDim.x + threadIdx.x;
    int stride = gridDim.x * blockDim.x;
    for (; e < N_EDGES; e += stride)
        atomicAdd(&cnt[__ldg(dst + e)], 1);
}

// One block per graph (grid=2, block=1024). Exclusive scan of counts.
__global__ __launch_bounds__(1024)
void k_scan() {
    const int g = blockIdx.x;                    // graph id
    const int* cnt = g_cnt + g * N_NODES;
    int* offs = g_offs + g * (N_NODES + 1);
    __shared__ int sums[1024];

    const int t = threadIdx.x;
    const int CHUNK = (N_NODES + 1023) / 1024;   // 49
    int beg = t * CHUNK;
    int end = min(beg + CHUNK, N_NODES);

    int s = 0;
    for (int i = beg; i < end; i++) s += cnt[i];
    sums[t] = s;
    __syncthreads();
    // Hillis-Steele inclusive scan
    for (int off = 1; off < 1024; off <<= 1) {
        int v = (t >= off) ? sums[t - off] : 0;
        __syncthreads();
        sums[t] += v;
        __syncthreads();
    }
    int run = (t == 0) ? 0 : sums[t - 1];
    for (int i = beg; i < end; i++) { offs[i] = run; run += cnt[i]; }
    if (end == N_NODES) offs[N_NODES] = run;
}

// dinv = rsqrt(1 + indegree); cursor = offs (reset every call for graph replay)
__global__ void k_prep() {
    int i = blockIdx.x * blockDim.x + threadIdx.x;
    if (i >= 2 * N_NODES) return;
    g_dinv[i] = rsqrtf(1.0f + (float)g_cnt[i]);
    int gph = (i >= N_NODES) ? 1 : 0;
    int local = i - gph * N_NODES;
    g_cur[i] = g_offs[gph * (N_NODES + 1) + local];
}

__global__ void k_fill(const int* __restrict__ src, const int* __restrict__ dst,
                       int* __restrict__ cur, int* __restrict__ csr) {
    int e = blockIdx.x * blockDim.x + threadIdx.x;
    int stride = gridDim.x * blockDim.x;
    for (; e < N_EDGES; e += stride) {
        int d = __ldg(dst + e);
        int p = atomicAdd(&cur[d], 1);
        csr[p] = __ldg(src + e);
    }
}

// ---------------------------------------------------------------------------
// GEMM: hs[m][:] = (x[m][:] @ W) * dinv[m]
// Block tile 64(M) x 128(N), K=128 in two 64-chunks. smem 48KB.
// ---------------------------------------------------------------------------
__global__ __launch_bounds__(256)
void k_gemm_scale(const float* __restrict__ x, const float* __restrict__ W,
                  const float* __restrict__ dinv, float* __restrict__ hs) {
    __shared__ float Wsh[64 * 128];
    __shared__ float xsh[64 * 64];

    const int tid = threadIdx.x;
    const int ty = tid >> 4;     // 0..15 -> 4 rows each
    const int tx = tid & 15;     // 0..15 -> 8 cols each
    const int row0 = blockIdx.x * BM;

    float a[4][8];
#pragma unroll
    for (int i = 0; i < 4; i++)
#pragma unroll
        for (int j = 0; j < 8; j++) a[i][j] = 0.0f;

    for (int kt = 0; kt < 2; kt++) {
        const float4* Wg = (const float4*)(W + kt * 64 * 128);
        float4* Ws4 = (float4*)Wsh;
#pragma unroll
        for (int r = 0; r < 8; r++)
            Ws4[tid + r * 256] = Wg[tid + r * 256];

        float4* xs4 = (float4*)xsh;
#pragma unroll
        for (int r = 0; r < 4; r++) {
            int f = tid + r * 256;
            int rr = f >> 4;
            int c4 = f & 15;
            int grow = row0 + rr;
            float4 v = make_float4(0.f, 0.f, 0.f, 0.f);
            if (grow < N_NODES)
                v = ((const float4*)(x + (size_t)grow * DIM + kt * 64))[c4];
            xs4[f] = v;
        }
        __syncthreads();

#pragma unroll 8
        for (int k = 0; k < 64; k++) {
            float xv[4];
#pragma unroll
            for (int i = 0; i < 4; i++) xv[i] = xsh[(ty * 4 + i) * 64 + k];
            float4 w0 = ((const float4*)Wsh)[k * 32 + tx * 2];
            float4 w1 = ((const float4*)Wsh)[k * 32 + tx * 2 + 1];
            float wv[8] = {w0.x, w0.y, w0.z, w0.w, w1.x, w1.y, w1.z, w1.w};
#pragma unroll
            for (int i = 0; i < 4; i++)
#pragma unroll
                for (int j = 0; j < 8; j++)
                    a[i][j] = fmaf(xv[i], wv[j], a[i][j]);
        }
        __syncthreads();
    }

#pragma unroll
    for (int i = 0; i < 4; i++) {
        int row = row0 + ty * 4 + i;
        if (row >= N_NODES) continue;
        float d = __ldg(dinv + row);
        float4 o0 = make_float4(a[i][0] * d, a[i][1] * d, a[i][2] * d, a[i][3] * d);
        float4 o1 = make_float4(a[i][4] * d, a[i][5] * d, a[i][6] * d, a[i][7] * d);
        float4* hrow = (float4*)(hs + (size_t)row * DIM);
        hrow[tx * 2]     = o0;
        hrow[tx * 2 + 1] = o1;
    }
}

// ---------------------------------------------------------------------------
// Aggregate + finalize (fused): one warp per dst node, lane = float4 chunk.
// out[n] = (sum_{e: dst=n} hs[src_e] + hs[n]) * dinv[n] + b   (+ ReLU)
// 4 independent accumulator chains for MLP.
// ---------------------------------------------------------------------------
__device__ __forceinline__ float4 f4add(float4 a, float4 b) {
    return make_float4(a.x + b.x, a.y + b.y, a.z + b.z, a.w + b.w);
}

__global__ __launch_bounds__(256)
void k_aggregate(const int* __restrict__ offs, const int* __restrict__ csr,
                 const float* __restrict__ hs, const float* __restrict__ dinv,
                 const float* __restrict__ b, float* __restrict__ out, int do_relu) {
    int node = blockIdx.x * (blockDim.x >> 5) + (threadIdx.x >> 5);
    if (node >= N_NODES) return;
    int lane = threadIdx.x & 31;
    const float4* hs4 = (const float4*)hs;

    int beg = __ldg(offs + node);
    int end = __ldg(offs + node + 1);

    float4 a0 = __ldg(hs4 + (size_t)node * 32 + lane);  // self loop
    float4 a1 = make_float4(0.f, 0.f, 0.f, 0.f);
    float4 a2 = a1, a3 = a1;

    int e = beg;
    for (; e + 4 <= end; e += 4) {
        int s0 = __ldg(csr + e);
        int s1 = __ldg(csr + e + 1);
        int s2 = __ldg(csr + e + 2);
        int s3 = __ldg(csr + e + 3);
        float4 v0 = __ldg(hs4 + (size_t)s0 * 32 + lane);
        float4 v1 = __ldg(hs4 + (size_t)s1 * 32 + lane);
        float4 v2 = __ldg(hs4 + (size_t)s2 * 32 + lane);
        float4 v3 = __ldg(hs4 + (size_t)s3 * 32 + lane);
        a0 = f4add(a0, v0);
        a1 = f4add(a1, v1);
        a2 = f4add(a2, v2);
        a3 = f4add(a3, v3);
    }
    for (; e < end; e++) {
        int s = __ldg(csr + e);
        a0 = f4add(a0, __ldg(hs4 + (size_t)s * 32 + lane));
    }
    float4 acc = f4add(f4add(a0, a1), f4add(a2, a3));

    float d = __ldg(dinv + node);
    float4 bb = __ldg(((const float4*)b) + lane);
    float4 o;
    o.x = fmaf(acc.x, d, bb.x);
    o.y = fmaf(acc.y, d, bb.y);
    o.z = fmaf(acc.z, d, bb.z);
    o.w = fmaf(acc.w, d, bb.w);
    if (do_relu) {
        o.x = fmaxf(o.x, 0.f); o.y = fmaxf(o.y, 0.f);
        o.z = fmaxf(o.z, 0.f); o.w = fmaxf(o.w, 0.f);
    }
    ((float4*)out)[(size_t)node * 32 + lane] = o;
}

// ---------------------------------------------------------------------------
// Launch
// ---------------------------------------------------------------------------
static void run_layer(const float* x, const int* offs, const int* csr,
                      const float* W, const float* b, const float* dinv,
                      float* hs, float* out, int do_relu) {
    k_gemm_scale<<<(N_NODES + BM - 1) / BM, 256>>>(x, W, dinv, hs);
    k_aggregate<<<(N_NODES * 32 + 255) / 256, 256>>>(offs, csr, hs, dinv, b, out, do_relu);
}

extern "C" void kernel_launch(void* const* d_in, const int* in_sizes, int n_in,
                              void* d_out, int out_size) {
    const float* x1  = (const float*)d_in[0];
    const int*   ei1 = (const int*)  d_in[1];
    const float* x2  = (const float*)d_in[2];
    const int*   ei2 = (const int*)  d_in[3];
    const float* W0  = (const float*)d_in[4];
    const float* b0  = (const float*)d_in[5];
    const float* W1  = (const float*)d_in[6];
    const float* b1  = (const float*)d_in[7];
    float* out = (float*)d_out;

    const int* src1 = ei1;
    const int* dst1 = ei1 + N_EDGES;
    const int* src2 = ei2;
    const int* dst2 = ei2 + N_EDGES;

    int *cnt, *offs, *cur, *csr;
    float *dinv, *hs, *h;
    cudaGetSymbolAddress((void**)&cnt,  g_cnt);
    cudaGetSymbolAddress((void**)&offs, g_offs);
    cudaGetSymbolAddress((void**)&cur,  g_cur);
    cudaGetSymbolAddress((void**)&csr,  g_csr);
    cudaGetSymbolAddress((void**)&dinv, g_dinv);
    cudaGetSymbolAddress((void**)&hs,   g_hs);
    cudaGetSymbolAddress((void**)&h,    g_h);

    // --- CSR build for both graphs (reused across both layers) ---
    k_zero_cnt<<<(2 * N_NODES + 255) / 256, 256>>>();
    k_count<<<1024, 256>>>(dst1, cnt);
    k_count<<<1024, 256>>>(dst2, cnt + N_NODES);
    k_scan<<<2, 1024>>>();
    k_prep<<<(2 * N_NODES + 255) / 256, 256>>>();
    k_fill<<<1024, 256>>>(src1, dst1, cur,           csr);
    k_fill<<<1024, 256>>>(src2, dst2, cur + N_NODES, csr + N_EDGES);

    const int* offs1 = offs;
    const int* offs2 = offs + (N_NODES + 1);

    // Graph 1
    run_layer(x1, offs1, csr,           W0, b0, dinv,           hs, h,   1);
    run_layer(h,  offs1, csr,           W1, b1, dinv,           hs, out, 0);
    // Graph 2
    run_layer(x2, offs2, csr + N_EDGES, W0, b0, dinv + N_NODES, hs, h,   1);
    run_layer(h,  offs2, csr + N_EDGES, W1, b1, dinv + N_NODES, hs, out + (size_t)N_NODES * DIM, 0);
}

// round 5
// speedup vs baseline: 1.4549x; 1.1135x over previous
#include <cuda_runtime.h>
#include <cuda_bf16.h>

#define N_NODES 50000
#define DIM     128
#define N_EDGES 800000
#define BM      64
#define TILE    512
#define TILES_PER_G 98          // ceil(50000/512)
#define N_TILES (2 * TILES_PER_G)

// ---------------------------------------------------------------------------
// Scratch (device globals — no allocation allowed in kernel_launch)
// ---------------------------------------------------------------------------
__device__ int   g_cnt [2 * N_NODES];          // in-degree counts (per graph)
__device__ int   g_offs[2 * (N_NODES + 1)];    // CSR row offsets (per graph)
__device__ int   g_cur [2 * N_NODES];          // fill cursors
__device__ int   g_csr [2 * N_EDGES];          // src indices bucketed by dst
__device__ float g_dinv[2 * N_NODES];
__device__ float g_hs  [N_NODES * DIM];        // (x @ W) * dinv[row]
__device__ float g_h   [N_NODES * DIM];        // hidden layer activations
__device__ int   g_tilesum [N_TILES];
__device__ int   g_tilebase[N_TILES];

// ---------------------------------------------------------------------------
// CSR build
// ---------------------------------------------------------------------------
__global__ void k_zero_cnt() {
    int i = blockIdx.x * blockDim.x + threadIdx.x;
    if (i < 2 * N_NODES) g_cnt[i] = 0;
}

// Count in-degrees for BOTH graphs in one launch.
__global__ void k_count2(const int* __restrict__ dst1, const int* __restrict__ dst2) {
    int i = blockIdx.x * blockDim.x + threadIdx.x;
    int stride = gridDim.x * blockDim.x;
    for (; i < 2 * N_EDGES; i += stride) {
        if (i < N_EDGES) atomicAdd(&g_cnt[__ldg(dst1 + i)], 1);
        else             atomicAdd(&g_cnt[N_NODES + __ldg(dst2 + i - N_EDGES)], 1);
    }
}

// Phase 1: per-tile sums. grid = N_TILES, block = TILE.
__global__ __launch_bounds__(TILE)
void k_blocksum() {
    int g  = blockIdx.x / TILES_PER_G;
    int lt = blockIdx.x % TILES_PER_G;
    int li = lt * TILE + threadIdx.x;
    int c = (li < N_NODES) ? g_cnt[g * N_NODES + li] : 0;

    int lane = threadIdx.x & 31, w = threadIdx.x >> 5;
    for (int o = 16; o > 0; o >>= 1) c += __shfl_down_sync(~0u, c, o);
    __shared__ int ws[TILE / 32];
    if (lane == 0) ws[w] = c;
    __syncthreads();
    if (threadIdx.x == 0) {
        int s = 0;
#pragma unroll
        for (int i = 0; i < TILE / 32; i++) s += ws[i];
        g_tilesum[blockIdx.x] = s;
    }
}

// Phase 2: scan the tile sums (tiny; serial on smem by thread 0 per graph).
__global__ __launch_bounds__(256)
void k_scanbase() {
    __shared__ int s[N_TILES];
    if (threadIdx.x < N_TILES) s[threadIdx.x] = g_tilesum[threadIdx.x];
    __syncthreads();
    if (threadIdx.x < 2) {
        int g = threadIdx.x;
        int run = 0;
        for (int t = 0; t < TILES_PER_G; t++) {
            g_tilebase[g * TILES_PER_G + t] = run;
            run += s[g * TILES_PER_G + t];
        }
        g_offs[g * (N_NODES + 1) + N_NODES] = run;
    }
}

// Phase 3: per-tile exclusive scan -> offsets; fused dinv + cursor init.
__global__ __launch_bounds__(TILE)
void k_offsets() {
    int g  = blockIdx.x / TILES_PER_G;
    int lt = blockIdx.x % TILES_PER_G;
    int li = lt * TILE + threadIdx.x;
    int c = (li < N_NODES) ? g_cnt[g * N_NODES + li] : 0;

    int lane = threadIdx.x & 31, w = threadIdx.x >> 5;
    int v = c;
#pragma unroll
    for (int o = 1; o < 32; o <<= 1) {
        int t = __shfl_up_sync(~0u, v, o);
        if (lane >= o) v += t;
    }
    __shared__ int ws[TILE / 32];
    if (lane == 31) ws[w] = v;
    __syncthreads();
    if (w == 0 && lane < TILE / 32) {
        int s = ws[lane];
#pragma unroll
        for (int o = 1; o < TILE / 32; o <<= 1) {
            int t = __shfl_up_sync(0xffff, s, o);
            if (lane >= o) s += t;
        }
        ws[lane] = s;
    }
    __syncthreads();
    int excl = v - c + (w > 0 ? ws[w - 1] : 0);

    if (li < N_NODES) {
        int off = g_tilebase[blockIdx.x] + excl;
        g_offs[g * (N_NODES + 1) + li] = off;
        g_cur [g * N_NODES + li] = off;
        g_dinv[g * N_NODES + li] = rsqrtf(1.0f + (float)c);
    }
}

// Fill CSR for BOTH graphs in one launch.
__global__ void k_fill2(const int* __restrict__ src1, const int* __restrict__ dst1,
                        const int* __restrict__ src2, const int* __restrict__ dst2) {
    int i = blockIdx.x * blockDim.x + threadIdx.x;
    int stride = gridDim.x * blockDim.x;
    for (; i < 2 * N_EDGES; i += stride) {
        if (i < N_EDGES) {
            int d = __ldg(dst1 + i);
            int p = atomicAdd(&g_cur[d], 1);
            g_csr[p] = __ldg(src1 + i);
        } else {
            int e = i - N_EDGES;
            int d = __ldg(dst2 + e);
            int p = atomicAdd(&g_cur[N_NODES + d], 1);
            g_csr[N_EDGES + p] = __ldg(src2 + e);
        }
    }
}

// ---------------------------------------------------------------------------
// GEMM: hs[m][:] = (x[m][:] @ W) * dinv[m]
// Block tile 64(M) x 128(N), K=128 in two 64-chunks. smem 48KB.
// Inner loop: k unrolled by 4 with float4 x loads (3 vec-LDS per k).
// ---------------------------------------------------------------------------
__global__ __launch_bounds__(256)
void k_gemm_scale(const float* __restrict__ x, const float* __restrict__ W,
                  const float* __restrict__ dinv, float* __restrict__ hs) {
    __shared__ float Wsh[64 * 128];
    __shared__ float xsh[64 * 64];

    const int tid = threadIdx.x;
    const int ty = tid >> 4;     // 0..15 -> 4 rows each
    const int tx = tid & 15;     // 0..15 -> 8 cols each
    const int row0 = blockIdx.x * BM;

    float a[4][8];
#pragma unroll
    for (int i = 0; i < 4; i++)
#pragma unroll
        for (int j = 0; j < 8; j++) a[i][j] = 0.0f;

    for (int kt = 0; kt < 2; kt++) {
        const float4* Wg = (const float4*)(W + kt * 64 * 128);
        float4* Ws4 = (float4*)Wsh;
#pragma unroll
        for (int r = 0; r < 8; r++)
            Ws4[tid + r * 256] = Wg[tid + r * 256];

        float4* xs4 = (float4*)xsh;
#pragma unroll
        for (int r = 0; r < 4; r++) {
            int f = tid + r * 256;
            int rr = f >> 4;
            int c4 = f & 15;
            int grow = row0 + rr;
            float4 v = make_float4(0.f, 0.f, 0.f, 0.f);
            if (grow < N_NODES)
                v = ((const float4*)(x + (size_t)grow * DIM + kt * 64))[c4];
            xs4[f] = v;
        }
        __syncthreads();

        const float4* xr4 = (const float4*)xsh;
        const float4* wr4 = (const float4*)Wsh;
#pragma unroll 4
        for (int k4 = 0; k4 < 16; k4++) {
            float4 xr[4];
#pragma unroll
            for (int i = 0; i < 4; i++)
                xr[i] = xr4[(ty * 4 + i) * 16 + k4];
#pragma unroll
            for (int kk = 0; kk < 4; kk++) {
                int k = k4 * 4 + kk;
                float4 w0 = wr4[k * 32 + tx * 2];
                float4 w1 = wr4[k * 32 + tx * 2 + 1];
                float wv[8] = {w0.x, w0.y, w0.z, w0.w, w1.x, w1.y, w1.z, w1.w};
#pragma unroll
                for (int i = 0; i < 4; i++) {
                    float xv = ((const float*)&xr[i])[kk];
#pragma unroll
                    for (int j = 0; j < 8; j++)
                        a[i][j] = fmaf(xv, wv[j], a[i][j]);
                }
            }
        }
        __syncthreads();
    }

#pragma unroll
    for (int i = 0; i < 4; i++) {
        int row = row0 + ty * 4 + i;
        if (row >= N_NODES) continue;
        float d = __ldg(dinv + row);
        float4 o0 = make_float4(a[i][0] * d, a[i][1] * d, a[i][2] * d, a[i][3] * d);
        float4 o1 = make_float4(a[i][4] * d, a[i][5] * d, a[i][6] * d, a[i][7] * d);
        float4* hrow = (float4*)(hs + (size_t)row * DIM);
        hrow[tx * 2]     = o0;
        hrow[tx * 2 + 1] = o1;
    }
}

// ---------------------------------------------------------------------------
// Aggregate + finalize (fused): one warp per dst node, lane = float4 chunk.
// out[n] = (sum_{e: dst=n} hs[src_e] + hs[n]) * dinv[n] + b   (+ ReLU)
// ---------------------------------------------------------------------------
__device__ __forceinline__ float4 f4add(float4 a, float4 b) {
    return make_float4(a.x + b.x, a.y + b.y, a.z + b.z, a.w + b.w);
}

__global__ __launch_bounds__(256)
void k_aggregate(const int* __restrict__ offs, const int* __restrict__ csr,
                 const float* __restrict__ hs, const float* __restrict__ dinv,
                 const float* __restrict__ b, float* __restrict__ out, int do_relu) {
    int node = blockIdx.x * (blockDim.x >> 5) + (threadIdx.x >> 5);
    if (node >= N_NODES) return;
    int lane = threadIdx.x & 31;
    const float4* hs4 = (const float4*)hs;

    int beg = __ldg(offs + node);
    int end = __ldg(offs + node + 1);

    float4 a0 = __ldg(hs4 + (size_t)node * 32 + lane);  // self loop
    float4 a1 = make_float4(0.f, 0.f, 0.f, 0.f);
    float4 a2 = a1, a3 = a1;

    int e = beg;
    for (; e + 4 <= end; e += 4) {
        int s0 = __ldg(csr + e);
        int s1 = __ldg(csr + e + 1);
        int s2 = __ldg(csr + e + 2);
        int s3 = __ldg(csr + e + 3);
        float4 v0 = __ldg(hs4 + (size_t)s0 * 32 + lane);
        float4 v1 = __ldg(hs4 + (size_t)s1 * 32 + lane);
        float4 v2 = __ldg(hs4 + (size_t)s2 * 32 + lane);
        float4 v3 = __ldg(hs4 + (size_t)s3 * 32 + lane);
        a0 = f4add(a0, v0);
        a1 = f4add(a1, v1);
        a2 = f4add(a2, v2);
        a3 = f4add(a3, v3);
    }
    for (; e < end; e++) {
        int s = __ldg(csr + e);
        a0 = f4add(a0, __ldg(hs4 + (size_t)s * 32 + lane));
    }
    float4 acc = f4add(f4add(a0, a1), f4add(a2, a3));

    float d = __ldg(dinv + node);
    float4 bb = __ldg(((const float4*)b) + lane);
    float4 o;
    o.x = fmaf(acc.x, d, bb.x);
    o.y = fmaf(acc.y, d, bb.y);
    o.z = fmaf(acc.z, d, bb.z);
    o.w = fmaf(acc.w, d, bb.w);
    if (do_relu) {
        o.x = fmaxf(o.x, 0.f); o.y = fmaxf(o.y, 0.f);
        o.z = fmaxf(o.z, 0.f); o.w = fmaxf(o.w, 0.f);
    }
    ((float4*)out)[(size_t)node * 32 + lane] = o;
}

// ---------------------------------------------------------------------------
// Launch
// ---------------------------------------------------------------------------
static void run_layer(const float* x, const int* offs, const int* csr,
                      const float* W, const float* b, const float* dinv,
                      float* hs, float* out, int do_relu) {
    k_gemm_scale<<<(N_NODES + BM - 1) / BM, 256>>>(x, W, dinv, hs);
    k_aggregate<<<(N_NODES * 32 + 255) / 256, 256>>>(offs, csr, hs, dinv, b, out, do_relu);
}

extern "C" void kernel_launch(void* const* d_in, const int* in_sizes, int n_in,
                              void* d_out, int out_size) {
    const float* x1  = (const float*)d_in[0];
    const int*   ei1 = (const int*)  d_in[1];
    const float* x2  = (const float*)d_in[2];
    const int*   ei2 = (const int*)  d_in[3];
    const float* W0  = (const float*)d_in[4];
    const float* b0  = (const float*)d_in[5];
    const float* W1  = (const float*)d_in[6];
    const float* b1  = (const float*)d_in[7];
    float* out = (float*)d_out;

    const int* src1 = ei1;
    const int* dst1 = ei1 + N_EDGES;
    const int* src2 = ei2;
    const int* dst2 = ei2 + N_EDGES;

    int *offs, *csr;
    float *dinv, *hs, *h;
    cudaGetSymbolAddress((void**)&offs, g_offs);
    cudaGetSymbolAddress((void**)&csr,  g_csr);
    cudaGetSymbolAddress((void**)&dinv, g_dinv);
    cudaGetSymbolAddress((void**)&hs,   g_hs);
    cudaGetSymbolAddress((void**)&h,    g_h);

    // --- CSR build for both graphs (reused across both layers) ---
    k_zero_cnt<<<(2 * N_NODES + 255) / 256, 256>>>();
    k_count2<<<2048, 256>>>(dst1, dst2);
    k_blocksum<<<N_TILES, TILE>>>();
    k_scanbase<<<1, 256>>>();
    k_offsets<<<N_TILES, TILE>>>();
    k_fill2<<<2048, 256>>>(src1, dst1, src2, dst2);

    const int* offs1 = offs;
    const int* offs2 = offs + (N_NODES + 1);

    // Graph 1
    run_layer(x1, offs1, csr,           W0, b0, dinv,           hs, h,   1);
    run_layer(h,  offs1, csr,           W1, b1, dinv,           hs, out, 0);
    // Graph 2
    run_layer(x2, offs2, csr + N_EDGES, W0, b0, dinv + N_NODES, hs, h,   1);
    run_layer(h,  offs2, csr + N_EDGES, W1, b1, dinv + N_NODES, hs, out + (size_t)N_NODES * DIM, 0);
}

// round 7
// speedup vs baseline: 1.8456x; 1.2685x over previous
#include <cuda_runtime.h>
#include <cuda_bf16.h>

#define N_NODES 50000
#define DIM     128
#define N_EDGES 800000
#define TILE    512
#define TILES_PER_G 98          // ceil(50000/512)
#define N_TILES (2 * TILES_PER_G)
#define GM      128             // GEMM block M

// ---------------------------------------------------------------------------
// Scratch (device globals — no allocation allowed in kernel_launch)
// ---------------------------------------------------------------------------
__device__ int    g_cnt [2 * N_NODES];
__device__ int    g_offs[2 * (N_NODES + 1)];
__device__ int    g_cur [2 * N_NODES];
__device__ int    g_csr [2 * N_EDGES];
__device__ float  g_dinv[2 * N_NODES];
__device__ float  g_hs  [N_NODES * DIM];
__device__ float  g_h   [N_NODES * DIM];
__device__ int    g_tilesum [N_TILES];
__device__ int    g_tilebase[N_TILES];
__device__ float4 g_Bpk[2 * 8192];   // pre-split W0/W1: [layer][kc(4)][ks(4)][n(128)][l4(4)]

// ---------------------------------------------------------------------------
// tf32 helpers
// ---------------------------------------------------------------------------
__device__ __forceinline__ unsigned f2tf(float f) {
    unsigned r;
    asm("cvt.rna.tf32.f32 %0, %1;" : "=r"(r) : "f"(f));
    return r;
}

__device__ __forceinline__ void mma8(float c[4], const unsigned a[4],
                                     unsigned b0, unsigned b1) {
    asm volatile(
        "mma.sync.aligned.m16n8k8.row.col.f32.tf32.tf32.f32 "
        "{%0,%1,%2,%3}, {%4,%5,%6,%7}, {%8,%9}, {%0,%1,%2,%3};"
        : "+f"(c[0]), "+f"(c[1]), "+f"(c[2]), "+f"(c[3])
        : "r"(a[0]), "r"(a[1]), "r"(a[2]), "r"(a[3]), "r"(b0), "r"(b1));
}

// ---------------------------------------------------------------------------
// W pre-split into MMA-fragment-native packed layout.
// For k0 = kc*32 + ks*8:  Bpk = {hi(W[k0+l4][n]), hi(W[k0+l4+4][n]),
//                               lo(W[k0+l4][n]), lo(W[k0+l4+4][n])}
// ---------------------------------------------------------------------------
__global__ void k_splitw(const float* __restrict__ W0, const float* __restrict__ W1) {
    int i = blockIdx.x * blockDim.x + threadIdx.x;
    if (i >= 16384) return;
    const float* W = (i < 8192) ? W0 : W1;
    int j  = i & 8191;
    int l4 = j & 3;
    int n  = (j >> 2) & 127;
    int ks = (j >> 9) & 3;
    int kc = j >> 11;
    int k0 = kc * 32 + ks * 8;
    float v0 = W[(k0 + l4) * 128 + n];
    float v1 = W[(k0 + l4 + 4) * 128 + n];
    unsigned h0 = f2tf(v0), h1 = f2tf(v1);
    unsigned l0 = f2tf(v0 - __uint_as_float(h0));
    unsigned l1 = f2tf(v1 - __uint_as_float(h1));
    g_Bpk[i] = make_float4(__uint_as_float(h0), __uint_as_float(h1),
                           __uint_as_float(l0), __uint_as_float(l1));
}

// ---------------------------------------------------------------------------
// CSR build
// ---------------------------------------------------------------------------
__global__ void k_zero_cnt() {
    int i = blockIdx.x * blockDim.x + threadIdx.x;
    if (i < 2 * N_NODES) g_cnt[i] = 0;
}

__global__ void k_count2(const int* __restrict__ dst1, const int* __restrict__ dst2) {
    int i = blockIdx.x * blockDim.x + threadIdx.x;
    int stride = gridDim.x * blockDim.x;
    for (; i < 2 * N_EDGES; i += stride) {
        if (i < N_EDGES) atomicAdd(&g_cnt[__ldg(dst1 + i)], 1);
        else             atomicAdd(&g_cnt[N_NODES + __ldg(dst2 + i - N_EDGES)], 1);
    }
}

__global__ __launch_bounds__(TILE)
void k_blocksum() {
    int g  = blockIdx.x / TILES_PER_G;
    int lt = blockIdx.x % TILES_PER_G;
    int li = lt * TILE + threadIdx.x;
    int c = (li < N_NODES) ? g_cnt[g * N_NODES + li] : 0;

    int lane = threadIdx.x & 31, w = threadIdx.x >> 5;
    for (int o = 16; o > 0; o >>= 1) c += __shfl_down_sync(~0u, c, o);
    __shared__ int ws[TILE / 32];
    if (lane == 0) ws[w] = c;
    __syncthreads();
    if (threadIdx.x == 0) {
        int s = 0;
#pragma unroll
        for (int i = 0; i < TILE / 32; i++) s += ws[i];
        g_tilesum[blockIdx.x] = s;
    }
}

__global__ __launch_bounds__(256)
void k_scanbase() {
    __shared__ int s[N_TILES];
    if (threadIdx.x < N_TILES) s[threadIdx.x] = g_tilesum[threadIdx.x];
    __syncthreads();
    if (threadIdx.x < 2) {
        int g = threadIdx.x;
        int run = 0;
        for (int t = 0; t < TILES_PER_G; t++) {
            g_tilebase[g * TILES_PER_G + t] = run;
            run += s[g * TILES_PER_G + t];
        }
        g_offs[g * (N_NODES + 1) + N_NODES] = run;
    }
}

__global__ __launch_bounds__(TILE)
void k_offsets() {
    int g  = blockIdx.x / TILES_PER_G;
    int lt = blockIdx.x % TILES_PER_G;
    int li = lt * TILE + threadIdx.x;
    int c = (li < N_NODES) ? g_cnt[g * N_NODES + li] : 0;

    int lane = threadIdx.x & 31, w = threadIdx.x >> 5;
    int v = c;
#pragma unroll
    for (int o = 1; o < 32; o <<= 1) {
        int t = __shfl_up_sync(~0u, v, o);
        if (lane >= o) v += t;
    }
    __shared__ int ws[TILE / 32];
    if (lane == 31) ws[w] = v;
    __syncthreads();
    if (w == 0 && lane < TILE / 32) {
        int s = ws[lane];
#pragma unroll
        for (int o = 1; o < TILE / 32; o <<= 1) {
            int t = __shfl_up_sync(0xffff, s, o);
            if (lane >= o) s += t;
        }
        ws[lane] = s;
    }
    __syncthreads();
    int excl = v - c + (w > 0 ? ws[w - 1] : 0);

    if (li < N_NODES) {
        int off = g_tilebase[blockIdx.x] + excl;
        g_offs[g * (N_NODES + 1) + li] = off;
        g_cur [g * N_NODES + li] = off;
        g_dinv[g * N_NODES + li] = rsqrtf(1.0f + (float)c);
    }
}

__global__ void k_fill2(const int* __restrict__ src1, const int* __restrict__ dst1,
                        const int* __restrict__ src2, const int* __restrict__ dst2) {
    int i = blockIdx.x * blockDim.x + threadIdx.x;
    int stride = gridDim.x * blockDim.x;
    for (; i < 2 * N_EDGES; i += stride) {
        if (i < N_EDGES) {
            int d = __ldg(dst1 + i);
            int p = atomicAdd(&g_cur[d], 1);
            g_csr[p] = __ldg(src1 + i);
        } else {
            int e = i - N_EDGES;
            int d = __ldg(dst2 + e);
            int p = atomicAdd(&g_cur[N_NODES + d], 1);
            g_csr[N_EDGES + p] = __ldg(src2 + e);
        }
    }
}

// ---------------------------------------------------------------------------
// GEMM (3xTF32 tensor cores): hs[m][:] = (x[m][:] @ W) * dinv[m]
// Block 128(M) x 128(N), 256 threads = 8 warps (4M x 2N), warp tile 32x64.
// K in 4 chunks of 32; per chunk: x tile 128x32 (swizzled float4), W packed.
// smem = 16KB + 32KB = 48KB static.
// ---------------------------------------------------------------------------
__global__ __launch_bounds__(256)
void k_gemm_tf32(const float* __restrict__ x, const float4* __restrict__ Bpk,
                 const float* __restrict__ dinv, float* __restrict__ hs) {
    __shared__ float4 xs4[128 * 8];   // [m][c'], c' = c ^ (m&7)
    __shared__ float4 Bs[2048];       // [ks][n][l4]

    const int tid  = threadIdx.x;
    const int lane = tid & 31;
    const int wid  = tid >> 5;
    const int g    = lane >> 2;
    const int l4   = lane & 3;
    const int wm   = (wid & 3) * 32;
    const int wn   = (wid >> 2) * 64;
    const int m0   = blockIdx.x * GM;

    float c[2][8][4];
#pragma unroll
    for (int mf = 0; mf < 2; mf++)
#pragma unroll
        for (int nb = 0; nb < 8; nb++)
#pragma unroll
            for (int q = 0; q < 4; q++) c[mf][nb][q] = 0.0f;

    for (int kc = 0; kc < 4; kc++) {
        // B chunk: straight copy (already fragment-packed)
#pragma unroll
        for (int j = 0; j < 8; j++)
            Bs[tid + j * 256] = __ldg(Bpk + kc * 2048 + tid + j * 256);
        // x chunk: swizzled store
#pragma unroll
        for (int i = 0; i < 4; i++) {
            int f = i * 256 + tid;
            int r = f >> 3, cc = f & 7;
            int R = m0 + r;
            float4 v = make_float4(0.f, 0.f, 0.f, 0.f);
            if (R < N_NODES)
                v = __ldg((const float4*)x + (size_t)R * 32 + kc * 8 + cc);
            xs4[r * 8 + (cc ^ (r & 7))] = v;
        }
        __syncthreads();

#pragma unroll
        for (int ks = 0; ks < 4; ks++) {
            unsigned ahi[2][4], alo[2][4];
#pragma unroll
            for (int mf = 0; mf < 2; mf++) {
                int r0 = wm + mf * 16 + g;
                int r1 = r0 + 8;
                const float* p0  = (const float*)&xs4[r0 * 8 + ((2 * ks)     ^ g)];
                const float* p0b = (const float*)&xs4[r0 * 8 + ((2 * ks + 1) ^ g)];
                const float* p1  = (const float*)&xs4[r1 * 8 + ((2 * ks)     ^ g)];
                const float* p1b = (const float*)&xs4[r1 * 8 + ((2 * ks + 1) ^ g)];
                float a0 = p0[l4], a1 = p1[l4], a2 = p0b[l4], a3 = p1b[l4];
                ahi[mf][0] = f2tf(a0); alo[mf][0] = f2tf(a0 - __uint_as_float(ahi[mf][0]));
                ahi[mf][1] = f2tf(a1); alo[mf][1] = f2tf(a1 - __uint_as_float(ahi[mf][1]));
                ahi[mf][2] = f2tf(a2); alo[mf][2] = f2tf(a2 - __uint_as_float(ahi[mf][2]));
                ahi[mf][3] = f2tf(a3); alo[mf][3] = f2tf(a3 - __uint_as_float(ahi[mf][3]));
            }
#pragma unroll
            for (int nb = 0; nb < 8; nb++) {
                // FIX (R6 bug): include the warp's N offset `wn` — B fragment
                // column must match the epilogue's output column base.
                uint4 b = *(const uint4*)&Bs[ks * 512 + (wn + nb * 8 + g) * 4 + l4];
#pragma unroll
                for (int mf = 0; mf < 2; mf++) {
                    mma8(c[mf][nb], ahi[mf], b.x, b.y);   // hi * hi
                    mma8(c[mf][nb], ahi[mf], b.z, b.w);   // hi * lo
                    mma8(c[mf][nb], alo[mf], b.x, b.y);   // lo * hi
                }
            }
        }
        __syncthreads();
    }

    // Epilogue: scale by dinv[row], store fp32
#pragma unroll
    for (int mf = 0; mf < 2; mf++) {
        int R0 = m0 + wm + mf * 16 + g;
        int R1 = R0 + 8;
        float d0 = (R0 < N_NODES) ? __ldg(dinv + R0) : 0.f;
        float d1 = (R1 < N_NODES) ? __ldg(dinv + R1) : 0.f;
#pragma unroll
        for (int nb = 0; nb < 8; nb++) {
            int col = wn + nb * 8 + 2 * l4;
            if (R0 < N_NODES) {
                float2 o = make_float2(c[mf][nb][0] * d0, c[mf][nb][1] * d0);
                *(float2*)(hs + (size_t)R0 * 128 + col) = o;
            }
            if (R1 < N_NODES) {
                float2 o = make_float2(c[mf][nb][2] * d1, c[mf][nb][3] * d1);
                *(float2*)(hs + (size_t)R1 * 128 + col) = o;
            }
        }
    }
}

// ---------------------------------------------------------------------------
// Aggregate + finalize (fused): one warp per dst node, lane = float4 chunk.
// out[n] = (sum_{e: dst=n} hs[src_e] + hs[n]) * dinv[n] + b   (+ ReLU)
// ---------------------------------------------------------------------------
__device__ __forceinline__ float4 f4add(float4 a, float4 b) {
    return make_float4(a.x + b.x, a.y + b.y, a.z + b.z, a.w + b.w);
}

__global__ __launch_bounds__(256)
void k_aggregate(const int* __restrict__ offs, const int* __restrict__ csr,
                 const float* __restrict__ hs, const float* __restrict__ dinv,
                 const float* __restrict__ b, float* __restrict__ out, int do_relu) {
    int node = blockIdx.x * (blockDim.x >> 5) + (threadIdx.x >> 5);
    if (node >= N_NODES) return;
    int lane = threadIdx.x & 31;
    const float4* hs4 = (const float4*)hs;

    int beg = __ldg(offs + node);
    int end = __ldg(offs + node + 1);

    float4 a0 = __ldg(hs4 + (size_t)node * 32 + lane);  // self loop
    float4 a1 = make_float4(0.f, 0.f, 0.f, 0.f);
    float4 a2 = a1, a3 = a1;

    int e = beg;
    for (; e + 4 <= end; e += 4) {
        int s0 = __ldg(csr + e);
        int s1 = __ldg(csr + e + 1);
        int s2 = __ldg(csr + e + 2);
        int s3 = __ldg(csr + e + 3);
        float4 v0 = __ldg(hs4 + (size_t)s0 * 32 + lane);
        float4 v1 = __ldg(hs4 + (size_t)s1 * 32 + lane);
        float4 v2 = __ldg(hs4 + (size_t)s2 * 32 + lane);
        float4 v3 = __ldg(hs4 + (size_t)s3 * 32 + lane);
        a0 = f4add(a0, v0);
        a1 = f4add(a1, v1);
        a2 = f4add(a2, v2);
        a3 = f4add(a3, v3);
    }
    for (; e < end; e++) {
        int s = __ldg(csr + e);
        a0 = f4add(a0, __ldg(hs4 + (size_t)s * 32 + lane));
    }
    float4 acc = f4add(f4add(a0, a1), f4add(a2, a3));

    float d = __ldg(dinv + node);
    float4 bb = __ldg(((const float4*)b) + lane);
    float4 o;
    o.x = fmaf(acc.x, d, bb.x);
    o.y = fmaf(acc.y, d, bb.y);
    o.z = fmaf(acc.z, d, bb.z);
    o.w = fmaf(acc.w, d, bb.w);
    if (do_relu) {
        o.x = fmaxf(o.x, 0.f); o.y = fmaxf(o.y, 0.f);
        o.z = fmaxf(o.z, 0.f); o.w = fmaxf(o.w, 0.f);
    }
    ((float4*)out)[(size_t)node * 32 + lane] = o;
}

// ---------------------------------------------------------------------------
// Launch
// ---------------------------------------------------------------------------
static void run_layer(const float* x, const int* offs, const int* csr,
                      const float4* Bpk, const float* b, const float* dinv,
                      float* hs, float* out, int do_relu) {
    k_gemm_tf32<<<(N_NODES + GM - 1) / GM, 256>>>(x, Bpk, dinv, hs);
    k_aggregate<<<(N_NODES * 32 + 255) / 256, 256>>>(offs, csr, hs, dinv, b, out, do_relu);
}

extern "C" void kernel_launch(void* const* d_in, const int* in_sizes, int n_in,
                              void* d_out, int out_size) {
    const float* x1  = (const float*)d_in[0];
    const int*   ei1 = (const int*)  d_in[1];
    const float* x2  = (const float*)d_in[2];
    const int*   ei2 = (const int*)  d_in[3];
    const float* W0  = (const float*)d_in[4];
    const float* b0  = (const float*)d_in[5];
    const float* W1  = (const float*)d_in[6];
    const float* b1  = (const float*)d_in[7];
    float* out = (float*)d_out;

    const int* src1 = ei1;
    const int* dst1 = ei1 + N_EDGES;
    const int* src2 = ei2;
    const int* dst2 = ei2 + N_EDGES;

    int *offs, *csr;
    float *dinv, *hs, *h;
    float4* Bpk;
    cudaGetSymbolAddress((void**)&offs, g_offs);
    cudaGetSymbolAddress((void**)&csr,  g_csr);
    cudaGetSymbolAddress((void**)&dinv, g_dinv);
    cudaGetSymbolAddress((void**)&hs,   g_hs);
    cudaGetSymbolAddress((void**)&h,    g_h);
    cudaGetSymbolAddress((void**)&Bpk,  g_Bpk);

    // --- W split + CSR build (CSR reused across both layers) ---
    k_splitw<<<64, 256>>>(W0, W1);
    k_zero_cnt<<<(2 * N_NODES + 255) / 256, 256>>>();
    k_count2<<<2048, 256>>>(dst1, dst2);
    k_blocksum<<<N_TILES, TILE>>>();
    k_scanbase<<<1, 256>>>();
    k_offsets<<<N_TILES, TILE>>>();
    k_fill2<<<2048, 256>>>(src1, dst1, src2, dst2);

    const int* offs1 = offs;
    const int* offs2 = offs + (N_NODES + 1);

    // Graph 1
    run_layer(x1, offs1, csr,           Bpk,        b0, dinv,           hs, h,   1);
    run_layer(h,  offs1, csr,           Bpk + 8192, b1, dinv,           hs, out, 0);
    // Graph 2
    run_layer(x2, offs2, csr + N_EDGES, Bpk,        b0, dinv + N_NODES, hs, h,   1);
    run_layer(h,  offs2, csr + N_EDGES, Bpk + 8192, b1, dinv + N_NODES, hs, out + (size_t)N_NODES * DIM, 0);
}

// round 8
// speedup vs baseline: 1.8604x; 1.0080x over previous
#include <cuda_runtime.h>
#include <cuda_fp16.h>
#include <cuda_bf16.h>

#define N_NODES 50000
#define DIM     128
#define N_EDGES 800000
#define TILE    512
#define TILES_PER_G 98          // ceil(50000/512)
#define N_TILES (2 * TILES_PER_G)
#define GM      128             // GEMM block M
#define NBLK    ((N_NODES + GM - 1) / GM)   // 391

// ---------------------------------------------------------------------------
// Scratch (device globals — no allocation allowed in kernel_launch)
// ---------------------------------------------------------------------------
__device__ int    g_cnt [2 * N_NODES];
__device__ int    g_offs[2 * (N_NODES + 1)];
__device__ int    g_cur [2 * N_NODES];
__device__ int    g_csr [2 * N_EDGES];
__device__ float  g_dinv[2 * N_NODES];
__device__ __half g_hsA [N_NODES * DIM];     // (x @ W) * dinv, graph 1 (fp16)
__device__ __half g_hsB [N_NODES * DIM];     // graph 2
__device__ float  g_h1  [N_NODES * DIM];     // hidden activations graph 1
__device__ float  g_h2  [N_NODES * DIM];     // graph 2
__device__ int    g_tilesum [N_TILES];
__device__ int    g_tilebase[N_TILES];
__device__ float4 g_Bpk[2 * 8192];   // pre-split W0/W1: [layer][kc(4)][ks(4)][n(128)][l4(4)]

// ---------------------------------------------------------------------------
// tf32 helpers
// ---------------------------------------------------------------------------
__device__ __forceinline__ unsigned f2tf(float f) {
    unsigned r;
    asm("cvt.rna.tf32.f32 %0, %1;" : "=r"(r) : "f"(f));
    return r;
}

__device__ __forceinline__ void mma8(float c[4], const unsigned a[4],
                                     unsigned b0, unsigned b1) {
    asm volatile(
        "mma.sync.aligned.m16n8k8.row.col.f32.tf32.tf32.f32 "
        "{%0,%1,%2,%3}, {%4,%5,%6,%7}, {%8,%9}, {%0,%1,%2,%3};"
        : "+f"(c[0]), "+f"(c[1]), "+f"(c[2]), "+f"(c[3])
        : "r"(a[0]), "r"(a[1]), "r"(a[2]), "r"(a[3]), "r"(b0), "r"(b1));
}

// ---------------------------------------------------------------------------
// W pre-split into MMA-fragment-native packed layout.
// ---------------------------------------------------------------------------
__global__ void k_splitw(const float* __restrict__ W0, const float* __restrict__ W1) {
    int i = blockIdx.x * blockDim.x + threadIdx.x;
    if (i >= 16384) return;
    const float* W = (i < 8192) ? W0 : W1;
    int j  = i & 8191;
    int l4 = j & 3;
    int n  = (j >> 2) & 127;
    int ks = (j >> 9) & 3;
    int kc = j >> 11;
    int k0 = kc * 32 + ks * 8;
    float v0 = W[(k0 + l4) * 128 + n];
    float v1 = W[(k0 + l4 + 4) * 128 + n];
    unsigned h0 = f2tf(v0), h1 = f2tf(v1);
    unsigned l0 = f2tf(v0 - __uint_as_float(h0));
    unsigned l1 = f2tf(v1 - __uint_as_float(h1));
    g_Bpk[i] = make_float4(__uint_as_float(h0), __uint_as_float(h1),
                           __uint_as_float(l0), __uint_as_float(l1));
}

// ---------------------------------------------------------------------------
// CSR build
// ---------------------------------------------------------------------------
__global__ void k_zero_cnt() {
    int i = blockIdx.x * blockDim.x + threadIdx.x;
    if (i < 2 * N_NODES) g_cnt[i] = 0;
}

__global__ void k_count2(const int* __restrict__ dst1, const int* __restrict__ dst2) {
    int i = blockIdx.x * blockDim.x + threadIdx.x;
    int stride = gridDim.x * blockDim.x;
    for (; i < 2 * N_EDGES; i += stride) {
        if (i < N_EDGES) atomicAdd(&g_cnt[__ldg(dst1 + i)], 1);
        else             atomicAdd(&g_cnt[N_NODES + __ldg(dst2 + i - N_EDGES)], 1);
    }
}

__global__ __launch_bounds__(TILE)
void k_blocksum() {
    int g  = blockIdx.x / TILES_PER_G;
    int lt = blockIdx.x % TILES_PER_G;
    int li = lt * TILE + threadIdx.x;
    int c = (li < N_NODES) ? g_cnt[g * N_NODES + li] : 0;

    int lane = threadIdx.x & 31, w = threadIdx.x >> 5;
    for (int o = 16; o > 0; o >>= 1) c += __shfl_down_sync(~0u, c, o);
    __shared__ int ws[TILE / 32];
    if (lane == 0) ws[w] = c;
    __syncthreads();
    if (threadIdx.x == 0) {
        int s = 0;
#pragma unroll
        for (int i = 0; i < TILE / 32; i++) s += ws[i];
        g_tilesum[blockIdx.x] = s;
    }
}

__global__ __launch_bounds__(256)
void k_scanbase() {
    __shared__ int s[N_TILES];
    if (threadIdx.x < N_TILES) s[threadIdx.x] = g_tilesum[threadIdx.x];
    __syncthreads();
    if (threadIdx.x < 2) {
        int g = threadIdx.x;
        int run = 0;
        for (int t = 0; t < TILES_PER_G; t++) {
            g_tilebase[g * TILES_PER_G + t] = run;
            run += s[g * TILES_PER_G + t];
        }
        g_offs[g * (N_NODES + 1) + N_NODES] = run;
    }
}

__global__ __launch_bounds__(TILE)
void k_offsets() {
    int g  = blockIdx.x / TILES_PER_G;
    int lt = blockIdx.x % TILES_PER_G;
    int li = lt * TILE + threadIdx.x;
    int c = (li < N_NODES) ? g_cnt[g * N_NODES + li] : 0;

    int lane = threadIdx.x & 31, w = threadIdx.x >> 5;
    int v = c;
#pragma unroll
    for (int o = 1; o < 32; o <<= 1) {
        int t = __shfl_up_sync(~0u, v, o);
        if (lane >= o) v += t;
    }
    __shared__ int ws[TILE / 32];
    if (lane == 31) ws[w] = v;
    __syncthreads();
    if (w == 0 && lane < TILE / 32) {
        int s = ws[lane];
#pragma unroll
        for (int o = 1; o < TILE / 32; o <<= 1) {
            int t = __shfl_up_sync(0xffff, s, o);
            if (lane >= o) s += t;
        }
        ws[lane] = s;
    }
    __syncthreads();
    int excl = v - c + (w > 0 ? ws[w - 1] : 0);

    if (li < N_NODES) {
        int off = g_tilebase[blockIdx.x] + excl;
        g_offs[g * (N_NODES + 1) + li] = off;
        g_cur [g * N_NODES + li] = off;
        g_dinv[g * N_NODES + li] = rsqrtf(1.0f + (float)c);
    }
}

__global__ void k_fill2(const int* __restrict__ src1, const int* __restrict__ dst1,
                        const int* __restrict__ src2, const int* __restrict__ dst2) {
    int i = blockIdx.x * blockDim.x + threadIdx.x;
    int stride = gridDim.x * blockDim.x;
    for (; i < 2 * N_EDGES; i += stride) {
        if (i < N_EDGES) {
            int d = __ldg(dst1 + i);
            int p = atomicAdd(&g_cur[d], 1);
            g_csr[p] = __ldg(src1 + i);
        } else {
            int e = i - N_EDGES;
            int d = __ldg(dst2 + e);
            int p = atomicAdd(&g_cur[N_NODES + d], 1);
            g_csr[N_EDGES + p] = __ldg(src2 + e);
        }
    }
}

// ---------------------------------------------------------------------------
// GEMM (3xTF32, batched over both graphs): hs[m][:] = (x[m][:] @ W) * dinv[m]
// Blocks [0, NBLK) -> graph 1, [NBLK, 2*NBLK) -> graph 2. fp16 output.
// ---------------------------------------------------------------------------
__global__ __launch_bounds__(256)
void k_gemm_tf32(const float* __restrict__ xA, const float* __restrict__ xB,
                 const float4* __restrict__ Bpk, const float* __restrict__ dinvAB,
                 __half* __restrict__ hsA, __half* __restrict__ hsB) {
    __shared__ float4 xs4[128 * 8];   // [m][c'], c' = c ^ (m&7)
    __shared__ float4 Bs[2048];       // [ks][n][l4]

    const int tid  = threadIdx.x;
    const int lane = tid & 31;
    const int wid  = tid >> 5;
    const int g    = lane >> 2;
    const int l4   = lane & 3;
    const int wm   = (wid & 3) * 32;
    const int wn   = (wid >> 2) * 64;

    const int gph  = (blockIdx.x >= NBLK) ? 1 : 0;
    const int m0   = (blockIdx.x - gph * NBLK) * GM;
    const float* x = gph ? xB : xA;
    __half* hs     = gph ? hsB : hsA;
    const float* dinv = dinvAB + gph * N_NODES;

    float c[2][8][4];
#pragma unroll
    for (int mf = 0; mf < 2; mf++)
#pragma unroll
        for (int nb = 0; nb < 8; nb++)
#pragma unroll
            for (int q = 0; q < 4; q++) c[mf][nb][q] = 0.0f;

    for (int kc = 0; kc < 4; kc++) {
#pragma unroll
        for (int j = 0; j < 8; j++)
            Bs[tid + j * 256] = __ldg(Bpk + kc * 2048 + tid + j * 256);
#pragma unroll
        for (int i = 0; i < 4; i++) {
            int f = i * 256 + tid;
            int r = f >> 3, cc = f & 7;
            int R = m0 + r;
            float4 v = make_float4(0.f, 0.f, 0.f, 0.f);
            if (R < N_NODES)
                v = __ldg((const float4*)x + (size_t)R * 32 + kc * 8 + cc);
            xs4[r * 8 + (cc ^ (r & 7))] = v;
        }
        __syncthreads();

#pragma unroll
        for (int ks = 0; ks < 4; ks++) {
            unsigned ahi[2][4], alo[2][4];
#pragma unroll
            for (int mf = 0; mf < 2; mf++) {
                int r0 = wm + mf * 16 + g;
                int r1 = r0 + 8;
                const float* p0  = (const float*)&xs4[r0 * 8 + ((2 * ks)     ^ g)];
                const float* p0b = (const float*)&xs4[r0 * 8 + ((2 * ks + 1) ^ g)];
                const float* p1  = (const float*)&xs4[r1 * 8 + ((2 * ks)     ^ g)];
                const float* p1b = (const float*)&xs4[r1 * 8 + ((2 * ks + 1) ^ g)];
                float a0 = p0[l4], a1 = p1[l4], a2 = p0b[l4], a3 = p1b[l4];
                ahi[mf][0] = f2tf(a0); alo[mf][0] = f2tf(a0 - __uint_as_float(ahi[mf][0]));
                ahi[mf][1] = f2tf(a1); alo[mf][1] = f2tf(a1 - __uint_as_float(ahi[mf][1]));
                ahi[mf][2] = f2tf(a2); alo[mf][2] = f2tf(a2 - __uint_as_float(ahi[mf][2]));
                ahi[mf][3] = f2tf(a3); alo[mf][3] = f2tf(a3 - __uint_as_float(ahi[mf][3]));
            }
#pragma unroll
            for (int nb = 0; nb < 8; nb++) {
                uint4 b = *(const uint4*)&Bs[ks * 512 + (wn + nb * 8 + g) * 4 + l4];
#pragma unroll
                for (int mf = 0; mf < 2; mf++) {
                    mma8(c[mf][nb], ahi[mf], b.x, b.y);   // hi * hi
                    mma8(c[mf][nb], ahi[mf], b.z, b.w);   // hi * lo
                    mma8(c[mf][nb], alo[mf], b.x, b.y);   // lo * hi
                }
            }
        }
        __syncthreads();
    }

    // Epilogue: scale by dinv[row], store fp16
#pragma unroll
    for (int mf = 0; mf < 2; mf++) {
        int R0 = m0 + wm + mf * 16 + g;
        int R1 = R0 + 8;
        float d0 = (R0 < N_NODES) ? __ldg(dinv + R0) : 0.f;
        float d1 = (R1 < N_NODES) ? __ldg(dinv + R1) : 0.f;
#pragma unroll
        for (int nb = 0; nb < 8; nb++) {
            int col = wn + nb * 8 + 2 * l4;
            if (R0 < N_NODES) {
                __half2 o = __floats2half2_rn(c[mf][nb][0] * d0, c[mf][nb][1] * d0);
                *(__half2*)(hs + (size_t)R0 * 128 + col) = o;
            }
            if (R1 < N_NODES) {
                __half2 o = __floats2half2_rn(c[mf][nb][2] * d1, c[mf][nb][3] * d1);
                *(__half2*)(hs + (size_t)R1 * 128 + col) = o;
            }
        }
    }
}

// ---------------------------------------------------------------------------
// Aggregate + finalize (fused, batched over both graphs).
// One warp per dst node; lane = 4-dim chunk (uint2 = 4 halves per gather).
// out[n] = (sum_{e: dst=n} hs[src_e] + hs[n]) * dinv[n] + b   (+ ReLU)
// fp32 accumulation.
// ---------------------------------------------------------------------------
__device__ __forceinline__ float4 h4tof4(uint2 v) {
    float2 lo = __half22float2(*(const __half2*)&v.x);
    float2 hi = __half22float2(*(const __half2*)&v.y);
    return make_float4(lo.x, lo.y, hi.x, hi.y);
}
__device__ __forceinline__ float4 f4add(float4 a, float4 b) {
    return make_float4(a.x + b.x, a.y + b.y, a.z + b.z, a.w + b.w);
}

__global__ __launch_bounds__(256)
void k_aggregate(const __half* __restrict__ hsA, const __half* __restrict__ hsB,
                 const float* __restrict__ b,
                 float* __restrict__ outA, float* __restrict__ outB, int do_relu) {
    int gnode = blockIdx.x * (blockDim.x >> 5) + (threadIdx.x >> 5);
    if (gnode >= 2 * N_NODES) return;
    int gph  = (gnode >= N_NODES) ? 1 : 0;
    int node = gnode - gph * N_NODES;
    int lane = threadIdx.x & 31;

    const int* offs = g_offs + gph * (N_NODES + 1);
    const int* csr  = g_csr  + gph * N_EDGES;
    const uint2* hs2 = (const uint2*)(gph ? hsB : hsA);
    float* out = gph ? outB : outA;

    int beg = __ldg(offs + node);
    int end = __ldg(offs + node + 1);

    float4 a0 = h4tof4(__ldg(hs2 + (size_t)node * 32 + lane));  // self loop
    float4 a1 = make_float4(0.f, 0.f, 0.f, 0.f);
    float4 a2 = a1, a3 = a1;

    int e = beg;
    for (; e + 4 <= end; e += 4) {
        int s0 = __ldg(csr + e);
        int s1 = __ldg(csr + e + 1);
        int s2 = __ldg(csr + e + 2);
        int s3 = __ldg(csr + e + 3);
        uint2 v0 = __ldg(hs2 + (size_t)s0 * 32 + lane);
        uint2 v1 = __ldg(hs2 + (size_t)s1 * 32 + lane);
        uint2 v2 = __ldg(hs2 + (size_t)s2 * 32 + lane);
        uint2 v3 = __ldg(hs2 + (size_t)s3 * 32 + lane);
        a0 = f4add(a0, h4tof4(v0));
        a1 = f4add(a1, h4tof4(v1));
        a2 = f4add(a2, h4tof4(v2));
        a3 = f4add(a3, h4tof4(v3));
    }
    for (; e < end; e++) {
        int s = __ldg(csr + e);
        a0 = f4add(a0, h4tof4(__ldg(hs2 + (size_t)s * 32 + lane)));
    }
    float4 acc = f4add(f4add(a0, a1), f4add(a2, a3));

    float d = __ldg(g_dinv + gnode);
    float4 bb = __ldg(((const float4*)b) + lane);
    float4 o;
    o.x = fmaf(acc.x, d, bb.x);
    o.y = fmaf(acc.y, d, bb.y);
    o.z = fmaf(acc.z, d, bb.z);
    o.w = fmaf(acc.w, d, bb.w);
    if (do_relu) {
        o.x = fmaxf(o.x, 0.f); o.y = fmaxf(o.y, 0.f);
        o.z = fmaxf(o.z, 0.f); o.w = fmaxf(o.w, 0.f);
    }
    ((float4*)out)[(size_t)node * 32 + lane] = o;
}

// ---------------------------------------------------------------------------
// Launch
// ---------------------------------------------------------------------------
extern "C" void kernel_launch(void* const* d_in, const int* in_sizes, int n_in,
                              void* d_out, int out_size) {
    const float* x1  = (const float*)d_in[0];
    const int*   ei1 = (const int*)  d_in[1];
    const float* x2  = (const float*)d_in[2];
    const int*   ei2 = (const int*)  d_in[3];
    const float* W0  = (const float*)d_in[4];
    const float* b0  = (const float*)d_in[5];
    const float* W1  = (const float*)d_in[6];
    const float* b1  = (const float*)d_in[7];
    float* out = (float*)d_out;

    const int* src1 = ei1;
    const int* dst1 = ei1 + N_EDGES;
    const int* src2 = ei2;
    const int* dst2 = ei2 + N_EDGES;

    float *dinv, *h1, *h2;
    __half *hsA, *hsB;
    float4* Bpk;
    cudaGetSymbolAddress((void**)&dinv, g_dinv);
    cudaGetSymbolAddress((void**)&hsA,  g_hsA);
    cudaGetSymbolAddress((void**)&hsB,  g_hsB);
    cudaGetSymbolAddress((void**)&h1,   g_h1);
    cudaGetSymbolAddress((void**)&h2,   g_h2);
    cudaGetSymbolAddress((void**)&Bpk,  g_Bpk);

    // --- W split + CSR build (reused across both layers) ---
    k_splitw<<<64, 256>>>(W0, W1);
    k_zero_cnt<<<(2 * N_NODES + 255) / 256, 256>>>();
    k_count2<<<2048, 256>>>(dst1, dst2);
    k_blocksum<<<N_TILES, TILE>>>();
    k_scanbase<<<1, 256>>>();
    k_offsets<<<N_TILES, TILE>>>();
    k_fill2<<<2048, 256>>>(src1, dst1, src2, dst2);

    const int AGG_GRID = (2 * N_NODES * 32 + 255) / 256;

    // Layer 1 (both graphs batched)
    k_gemm_tf32<<<2 * NBLK, 256>>>(x1, x2, Bpk, dinv, hsA, hsB);
    k_aggregate<<<AGG_GRID, 256>>>(hsA, hsB, b0, h1, h2, 1);
    // Layer 2 (both graphs batched)
    k_gemm_tf32<<<2 * NBLK, 256>>>(h1, h2, Bpk + 8192, dinv, hsA, hsB);
    k_aggregate<<<AGG_GRID, 256>>>(hsA, hsB, b1, out, out + (size_t)N_NODES * DIM, 0);
}

// round 9
// speedup vs baseline: 1.8606x; 1.0001x over previous
#include <cuda_runtime.h>
#include <cuda_fp16.h>
#include <cuda_bf16.h>

#define N_NODES 50000
#define DIM     128
#define N_EDGES 800000
#define TILE    512
#define TILES_PER_G 98          // ceil(50000/512)
#define N_TILES (2 * TILES_PER_G)
#define GM      128             // GEMM block M
#define NBLK    ((N_NODES + GM - 1) / GM)   // 391

// ---------------------------------------------------------------------------
// Scratch (device globals — no allocation allowed in kernel_launch)
// ---------------------------------------------------------------------------
__device__ int    g_cnt [2 * N_NODES];
__device__ int    g_offs[2 * (N_NODES + 1)];
__device__ int    g_cur [2 * N_NODES];
__device__ int    g_csr [2 * N_EDGES];
__device__ float  g_dinv[2 * N_NODES];
__device__ __half g_hsA [N_NODES * DIM];     // x @ W  (unscaled, fp16), graph 1
__device__ __half g_hsB [N_NODES * DIM];     // graph 2
__device__ float  g_h1  [N_NODES * DIM];     // hidden activations graph 1
__device__ float  g_h2  [N_NODES * DIM];     // graph 2
__device__ int    g_tilesum [N_TILES];
__device__ int    g_tilebase[N_TILES];
__device__ float2 g_Bpk[2 * 8192];   // tf32(W0/W1), fragment-packed:
                                     // [layer][kc(4)][ks(4)][n(128)][l4(4)] = {hi(k), hi(k+4)}

// ---------------------------------------------------------------------------
// tf32 helpers
// ---------------------------------------------------------------------------
__device__ __forceinline__ unsigned f2tf(float f) {
    unsigned r;
    asm("cvt.rna.tf32.f32 %0, %1;" : "=r"(r) : "f"(f));
    return r;
}

__device__ __forceinline__ void mma8(float c[4], const unsigned a[4],
                                     unsigned b0, unsigned b1) {
    asm volatile(
        "mma.sync.aligned.m16n8k8.row.col.f32.tf32.tf32.f32 "
        "{%0,%1,%2,%3}, {%4,%5,%6,%7}, {%8,%9}, {%0,%1,%2,%3};"
        : "+f"(c[0]), "+f"(c[1]), "+f"(c[2]), "+f"(c[3])
        : "r"(a[0]), "r"(a[1]), "r"(a[2]), "r"(a[3]), "r"(b0), "r"(b1));
}

// ---------------------------------------------------------------------------
// W pre-pack (tf32-rounded, hi only): Bpk = {tf32(W[k0+l4][n]), tf32(W[k0+l4+4][n])}
// ---------------------------------------------------------------------------
__global__ void k_splitw(const float* __restrict__ W0, const float* __restrict__ W1) {
    int i = blockIdx.x * blockDim.x + threadIdx.x;
    if (i >= 16384) return;
    const float* W = (i < 8192) ? W0 : W1;
    int j  = i & 8191;
    int l4 = j & 3;
    int n  = (j >> 2) & 127;
    int ks = (j >> 9) & 3;
    int kc = j >> 11;
    int k0 = kc * 32 + ks * 8;
    g_Bpk[i] = make_float2(__uint_as_float(f2tf(W[(k0 + l4) * 128 + n])),
                           __uint_as_float(f2tf(W[(k0 + l4 + 4) * 128 + n])));
}

// ---------------------------------------------------------------------------
// CSR build
// ---------------------------------------------------------------------------
__global__ void k_zero_cnt() {
    int i = blockIdx.x * blockDim.x + threadIdx.x;
    if (i < 2 * N_NODES) g_cnt[i] = 0;
}

__global__ void k_count2(const int* __restrict__ dst1, const int* __restrict__ dst2) {
    int i = blockIdx.x * blockDim.x + threadIdx.x;
    int stride = gridDim.x * blockDim.x;
    for (; i < 2 * N_EDGES; i += stride) {
        if (i < N_EDGES) atomicAdd(&g_cnt[__ldg(dst1 + i)], 1);
        else             atomicAdd(&g_cnt[N_NODES + __ldg(dst2 + i - N_EDGES)], 1);
    }
}

__global__ __launch_bounds__(TILE)
void k_blocksum() {
    int g  = blockIdx.x / TILES_PER_G;
    int lt = blockIdx.x % TILES_PER_G;
    int li = lt * TILE + threadIdx.x;
    int c = (li < N_NODES) ? g_cnt[g * N_NODES + li] : 0;

    int lane = threadIdx.x & 31, w = threadIdx.x >> 5;
    for (int o = 16; o > 0; o >>= 1) c += __shfl_down_sync(~0u, c, o);
    __shared__ int ws[TILE / 32];
    if (lane == 0) ws[w] = c;
    __syncthreads();
    if (threadIdx.x == 0) {
        int s = 0;
#pragma unroll
        for (int i = 0; i < TILE / 32; i++) s += ws[i];
        g_tilesum[blockIdx.x] = s;
    }
}

__global__ __launch_bounds__(256)
void k_scanbase() {
    __shared__ int s[N_TILES];
    if (threadIdx.x < N_TILES) s[threadIdx.x] = g_tilesum[threadIdx.x];
    __syncthreads();
    if (threadIdx.x < 2) {
        int g = threadIdx.x;
        int run = 0;
        for (int t = 0; t < TILES_PER_G; t++) {
            g_tilebase[g * TILES_PER_G + t] = run;
            run += s[g * TILES_PER_G + t];
        }
        g_offs[g * (N_NODES + 1) + N_NODES] = run;
    }
}

__global__ __launch_bounds__(TILE)
void k_offsets() {
    int g  = blockIdx.x / TILES_PER_G;
    int lt = blockIdx.x % TILES_PER_G;
    int li = lt * TILE + threadIdx.x;
    int c = (li < N_NODES) ? g_cnt[g * N_NODES + li] : 0;

    int lane = threadIdx.x & 31, w = threadIdx.x >> 5;
    int v = c;
#pragma unroll
    for (int o = 1; o < 32; o <<= 1) {
        int t = __shfl_up_sync(~0u, v, o);
        if (lane >= o) v += t;
    }
    __shared__ int ws[TILE / 32];
    if (lane == 31) ws[w] = v;
    __syncthreads();
    if (w == 0 && lane < TILE / 32) {
        int s = ws[lane];
#pragma unroll
        for (int o = 1; o < TILE / 32; o <<= 1) {
            int t = __shfl_up_sync(0xffff, s, o);
            if (lane >= o) s += t;
        }
        ws[lane] = s;
    }
    __syncthreads();
    int excl = v - c + (w > 0 ? ws[w - 1] : 0);

    if (li < N_NODES) {
        int off = g_tilebase[blockIdx.x] + excl;
        g_offs[g * (N_NODES + 1) + li] = off;
        g_cur [g * N_NODES + li] = off;
        g_dinv[g * N_NODES + li] = rsqrtf(1.0f + (float)c);
    }
}

__global__ void k_fill2(const int* __restrict__ src1, const int* __restrict__ dst1,
                        const int* __restrict__ src2, const int* __restrict__ dst2) {
    int i = blockIdx.x * blockDim.x + threadIdx.x;
    int stride = gridDim.x * blockDim.x;
    for (; i < 2 * N_EDGES; i += stride) {
        if (i < N_EDGES) {
            int d = __ldg(dst1 + i);
            int p = atomicAdd(&g_cur[d], 1);
            g_csr[p] = __ldg(src1 + i);
        } else {
            int e = i - N_EDGES;
            int d = __ldg(dst2 + e);
            int p = atomicAdd(&g_cur[N_NODES + d], 1);
            g_csr[N_EDGES + p] = __ldg(src2 + e);
        }
    }
}

// ---------------------------------------------------------------------------
// GEMM (2-term TF32 split: xhi*W + xlo*W, W tf32-rounded; batched over graphs)
// hs[m][:] = x[m][:] @ W  (unscaled; dinv applied in aggregate). fp16 output.
// ---------------------------------------------------------------------------
__global__ __launch_bounds__(256)
void k_gemm_tf32(const float* __restrict__ xA, const float* __restrict__ xB,
                 const float2* __restrict__ Bpk,
                 __half* __restrict__ hsA, __half* __restrict__ hsB) {
    __shared__ float4 xs4[128 * 8];   // [m][c'], c' = c ^ (m&7)
    __shared__ float2 Bs[2048];       // [ks][n][l4] = {hi(k), hi(k+4)}

    const int tid  = threadIdx.x;
    const int lane = tid & 31;
    const int wid  = tid >> 5;
    const int g    = lane >> 2;
    const int l4   = lane & 3;
    const int wm   = (wid & 3) * 32;
    const int wn   = (wid >> 2) * 64;

    const int gph  = (blockIdx.x >= NBLK) ? 1 : 0;
    const int m0   = (blockIdx.x - gph * NBLK) * GM;
    const float* x = gph ? xB : xA;
    __half* hs     = gph ? hsB : hsA;

    float c[2][8][4];
#pragma unroll
    for (int mf = 0; mf < 2; mf++)
#pragma unroll
        for (int nb = 0; nb < 8; nb++)
#pragma unroll
            for (int q = 0; q < 4; q++) c[mf][nb][q] = 0.0f;

    for (int kc = 0; kc < 4; kc++) {
#pragma unroll
        for (int j = 0; j < 8; j++)
            Bs[tid + j * 256] = __ldg(Bpk + kc * 2048 + tid + j * 256);
#pragma unroll
        for (int i = 0; i < 4; i++) {
            int f = i * 256 + tid;
            int r = f >> 3, cc = f & 7;
            int R = m0 + r;
            float4 v = make_float4(0.f, 0.f, 0.f, 0.f);
            if (R < N_NODES)
                v = __ldg((const float4*)x + (size_t)R * 32 + kc * 8 + cc);
            xs4[r * 8 + (cc ^ (r & 7))] = v;
        }
        __syncthreads();

#pragma unroll
        for (int ks = 0; ks < 4; ks++) {
            unsigned ahi[2][4], alo[2][4];
#pragma unroll
            for (int mf = 0; mf < 2; mf++) {
                int r0 = wm + mf * 16 + g;
                int r1 = r0 + 8;
                const float* p0  = (const float*)&xs4[r0 * 8 + ((2 * ks)     ^ g)];
                const float* p0b = (const float*)&xs4[r0 * 8 + ((2 * ks + 1) ^ g)];
                const float* p1  = (const float*)&xs4[r1 * 8 + ((2 * ks)     ^ g)];
                const float* p1b = (const float*)&xs4[r1 * 8 + ((2 * ks + 1) ^ g)];
                float a0 = p0[l4], a1 = p1[l4], a2 = p0b[l4], a3 = p1b[l4];
                ahi[mf][0] = f2tf(a0); alo[mf][0] = f2tf(a0 - __uint_as_float(ahi[mf][0]));
                ahi[mf][1] = f2tf(a1); alo[mf][1] = f2tf(a1 - __uint_as_float(ahi[mf][1]));
                ahi[mf][2] = f2tf(a2); alo[mf][2] = f2tf(a2 - __uint_as_float(ahi[mf][2]));
                ahi[mf][3] = f2tf(a3); alo[mf][3] = f2tf(a3 - __uint_as_float(ahi[mf][3]));
            }
#pragma unroll
            for (int nb = 0; nb < 8; nb++) {
                uint2 b = *(const uint2*)&Bs[ks * 512 + (wn + nb * 8 + g) * 4 + l4];
#pragma unroll
                for (int mf = 0; mf < 2; mf++) {
                    mma8(c[mf][nb], ahi[mf], b.x, b.y);   // xhi * W
                    mma8(c[mf][nb], alo[mf], b.x, b.y);   // xlo * W
                }
            }
        }
        __syncthreads();
    }

    // Epilogue: store fp16 (no scaling)
#pragma unroll
    for (int mf = 0; mf < 2; mf++) {
        int R0 = m0 + wm + mf * 16 + g;
        int R1 = R0 + 8;
#pragma unroll
        for (int nb = 0; nb < 8; nb++) {
            int col = wn + nb * 8 + 2 * l4;
            if (R0 < N_NODES) {
                __half2 o = __floats2half2_rn(c[mf][nb][0], c[mf][nb][1]);
                *(__half2*)(hs + (size_t)R0 * 128 + col) = o;
            }
            if (R1 < N_NODES) {
                __half2 o = __floats2half2_rn(c[mf][nb][2], c[mf][nb][3]);
                *(__half2*)(hs + (size_t)R1 * 128 + col) = o;
            }
        }
    }
}

// ---------------------------------------------------------------------------
// Aggregate + finalize (fused, batched): one warp per dst node, lane = 4-dim
// chunk. 8 independent accumulator chains (MLP=8).
// out[n] = dinv[n]*( sum_e h[src_e]*dinv[src_e] + dinv[n]*h[n] ) + b  (+ ReLU)
// ---------------------------------------------------------------------------
__device__ __forceinline__ float4 h4tof4(uint2 v) {
    float2 lo = __half22float2(*(const __half2*)&v.x);
    float2 hi = __half22float2(*(const __half2*)&v.y);
    return make_float4(lo.x, lo.y, hi.x, hi.y);
}
__device__ __forceinline__ float4 f4add(float4 a, float4 b) {
    return make_float4(a.x + b.x, a.y + b.y, a.z + b.z, a.w + b.w);
}
__device__ __forceinline__ void f4fma(float4& a, float4 v, float s) {
    a.x = fmaf(v.x, s, a.x);
    a.y = fmaf(v.y, s, a.y);
    a.z = fmaf(v.z, s, a.z);
    a.w = fmaf(v.w, s, a.w);
}

__global__ __launch_bounds__(256)
void k_aggregate(const __half* __restrict__ hsA, const __half* __restrict__ hsB,
                 const float* __restrict__ b,
                 float* __restrict__ outA, float* __restrict__ outB, int do_relu) {
    int gnode = blockIdx.x * (blockDim.x >> 5) + (threadIdx.x >> 5);
    if (gnode >= 2 * N_NODES) return;
    int gph  = (gnode >= N_NODES) ? 1 : 0;
    int node = gnode - gph * N_NODES;
    int lane = threadIdx.x & 31;

    const int*   offs = g_offs + gph * (N_NODES + 1);
    const int*   csr  = g_csr  + gph * N_EDGES;
    const float* dinv = g_dinv + gph * N_NODES;
    const uint2* hs2  = (const uint2*)(gph ? hsB : hsA);
    float* out = gph ? outB : outA;

    int beg = __ldg(offs + node);
    int end = __ldg(offs + node + 1);
    float dd = __ldg(dinv + node);

    float4 a0 = make_float4(0.f, 0.f, 0.f, 0.f);
    float4 a1 = a0, a2 = a0, a3 = a0, a4 = a0, a5 = a0, a6 = a0, a7 = a0;
    // self loop: dd * h[node]
    f4fma(a0, h4tof4(__ldg(hs2 + (size_t)node * 32 + lane)), dd);

    int e = beg;
    for (; e + 8 <= end; e += 8) {
        int s0 = __ldg(csr + e);     int s1 = __ldg(csr + e + 1);
        int s2 = __ldg(csr + e + 2); int s3 = __ldg(csr + e + 3);
        int s4 = __ldg(csr + e + 4); int s5 = __ldg(csr + e + 5);
        int s6 = __ldg(csr + e + 6); int s7 = __ldg(csr + e + 7);
        uint2 v0 = __ldg(hs2 + (size_t)s0 * 32 + lane);
        uint2 v1 = __ldg(hs2 + (size_t)s1 * 32 + lane);
        uint2 v2 = __ldg(hs2 + (size_t)s2 * 32 + lane);
        uint2 v3 = __ldg(hs2 + (size_t)s3 * 32 + lane);
        uint2 v4 = __ldg(hs2 + (size_t)s4 * 32 + lane);
        uint2 v5 = __ldg(hs2 + (size_t)s5 * 32 + lane);
        uint2 v6 = __ldg(hs2 + (size_t)s6 * 32 + lane);
        uint2 v7 = __ldg(hs2 + (size_t)s7 * 32 + lane);
        float d0 = __ldg(dinv + s0), d1 = __ldg(dinv + s1);
        float d2 = __ldg(dinv + s2), d3 = __ldg(dinv + s3);
        float d4 = __ldg(dinv + s4), d5 = __ldg(dinv + s5);
        float d6 = __ldg(dinv + s6), d7 = __ldg(dinv + s7);
        f4fma(a0, h4tof4(v0), d0);  f4fma(a1, h4tof4(v1), d1);
        f4fma(a2, h4tof4(v2), d2);  f4fma(a3, h4tof4(v3), d3);
        f4fma(a4, h4tof4(v4), d4);  f4fma(a5, h4tof4(v5), d5);
        f4fma(a6, h4tof4(v6), d6);  f4fma(a7, h4tof4(v7), d7);
    }
    for (; e + 2 <= end; e += 2) {
        int s0 = __ldg(csr + e), s1 = __ldg(csr + e + 1);
        uint2 v0 = __ldg(hs2 + (size_t)s0 * 32 + lane);
        uint2 v1 = __ldg(hs2 + (size_t)s1 * 32 + lane);
        float d0 = __ldg(dinv + s0), d1 = __ldg(dinv + s1);
        f4fma(a0, h4tof4(v0), d0);
        f4fma(a1, h4tof4(v1), d1);
    }
    if (e < end) {
        int s = __ldg(csr + e);
        f4fma(a0, h4tof4(__ldg(hs2 + (size_t)s * 32 + lane)), __ldg(dinv + s));
    }
    float4 acc = f4add(f4add(f4add(a0, a1), f4add(a2, a3)),
                       f4add(f4add(a4, a5), f4add(a6, a7)));

    float4 bb = __ldg(((const float4*)b) + lane);
    float4 o;
    o.x = fmaf(acc.x, dd, bb.x);
    o.y = fmaf(acc.y, dd, bb.y);
    o.z = fmaf(acc.z, dd, bb.z);
    o.w = fmaf(acc.w, dd, bb.w);
    if (do_relu) {
        o.x = fmaxf(o.x, 0.f); o.y = fmaxf(o.y, 0.f);
        o.z = fmaxf(o.z, 0.f); o.w = fmaxf(o.w, 0.f);
    }
    ((float4*)out)[(size_t)node * 32 + lane] = o;
}

// ---------------------------------------------------------------------------
// Launch.  Order puts k_gemm_tf32 (layer 1) at launch index 3 so the fixed
// ncu window (-s 5 -c 1 -> 4th launch) finally profiles a dominant kernel.
// ---------------------------------------------------------------------------
extern "C" void kernel_launch(void* const* d_in, const int* in_sizes, int n_in,
                              void* d_out, int out_size) {
    const float* x1  = (const float*)d_in[0];
    const int*   ei1 = (const int*)  d_in[1];
    const float* x2  = (const float*)d_in[2];
    const int*   ei2 = (const int*)  d_in[3];
    const float* W0  = (const float*)d_in[4];
    const float* b0  = (const float*)d_in[5];
    const float* W1  = (const float*)d_in[6];
    const float* b1  = (const float*)d_in[7];
    float* out = (float*)d_out;

    const int* src1 = ei1;
    const int* dst1 = ei1 + N_EDGES;
    const int* src2 = ei2;
    const int* dst2 = ei2 + N_EDGES;

    float *h1, *h2;
    __half *hsA, *hsB;
    float2* Bpk;
    cudaGetSymbolAddress((void**)&hsA, g_hsA);
    cudaGetSymbolAddress((void**)&hsB, g_hsB);
    cudaGetSymbolAddress((void**)&h1,  g_h1);
    cudaGetSymbolAddress((void**)&h2,  g_h2);
    cudaGetSymbolAddress((void**)&Bpk, g_Bpk);

    // idx0..2: prep that GEMM1 doesn't depend on interleaved with its deps
    k_splitw<<<64, 256>>>(W0, W1);                         // 0
    k_zero_cnt<<<(2 * N_NODES + 255) / 256, 256>>>();      // 1
    k_count2<<<2048, 256>>>(dst1, dst2);                   // 2
    // idx3: layer-1 GEMM (profiled by ncu's fixed window)
    k_gemm_tf32<<<2 * NBLK, 256>>>(x1, x2, Bpk, hsA, hsB); // 3
    // rest of CSR build
    k_blocksum<<<N_TILES, TILE>>>();                       // 4
    k_scanbase<<<1, 256>>>();                              // 5
    k_offsets<<<N_TILES, TILE>>>();                        // 6
    k_fill2<<<2048, 256>>>(src1, dst1, src2, dst2);        // 7

    const int AGG_GRID = (2 * N_NODES * 32 + 255) / 256;

    k_aggregate<<<AGG_GRID, 256>>>(hsA, hsB, b0, h1, h2, 1);
    k_gemm_tf32<<<2 * NBLK, 256>>>(h1, h2, Bpk + 8192, hsA, hsB);
    k_aggregate<<<AGG_GRID, 256>>>(hsA, hsB, b1, out, out + (size_t)N_NODES * DIM, 0);
}

// round 10
// speedup vs baseline: 1.9886x; 1.0688x over previous
#include <cuda_runtime.h>
#include <cuda_fp16.h>
#include <cuda_bf16.h>

#define N_NODES 50000
#define DIM     128
#define N_EDGES 800000
#define TILE    512
#define TILES_PER_G 98          // ceil(50000/512)
#define N_TILES (2 * TILES_PER_G)
#define GM      128             // GEMM block M
#define NBLK    ((N_NODES + GM - 1) / GM)   // 391

// ---------------------------------------------------------------------------
// Scratch (device globals — no allocation allowed in kernel_launch)
// ---------------------------------------------------------------------------
__device__ int    g_cnt [2 * N_NODES];
__device__ int    g_offs[2 * (N_NODES + 1)];
__device__ int    g_cur [2 * N_NODES];
__device__ int    g_csr [2 * N_EDGES];
__device__ float  g_dinv[2 * N_NODES];
__device__ __half g_hsA [N_NODES * DIM];     // x @ W  (unscaled, fp16), graph 1
__device__ __half g_hsB [N_NODES * DIM];     // graph 2
__device__ float  g_h1  [N_NODES * DIM];     // hidden activations graph 1
__device__ float  g_h2  [N_NODES * DIM];     // graph 2
__device__ int    g_tilesum [N_TILES];
__device__ int    g_tilebase[N_TILES];
__device__ float2 g_Bpk[2 * 8192];   // tf32(W0/W1), fragment-packed:
                                     // [layer][kc(4)][ks(4)][n(128)][l4(4)] = {hi(k), hi(k+4)}

// ---------------------------------------------------------------------------
// tf32 helpers
// ---------------------------------------------------------------------------
__device__ __forceinline__ unsigned f2tf(float f) {
    unsigned r;
    asm("cvt.rna.tf32.f32 %0, %1;" : "=r"(r) : "f"(f));
    return r;
}

__device__ __forceinline__ void mma8(float c[4], const unsigned a[4],
                                     unsigned b0, unsigned b1) {
    asm volatile(
        "mma.sync.aligned.m16n8k8.row.col.f32.tf32.tf32.f32 "
        "{%0,%1,%2,%3}, {%4,%5,%6,%7}, {%8,%9}, {%0,%1,%2,%3};"
        : "+f"(c[0]), "+f"(c[1]), "+f"(c[2]), "+f"(c[3])
        : "r"(a[0]), "r"(a[1]), "r"(a[2]), "r"(a[3]), "r"(b0), "r"(b1));
}

// ---------------------------------------------------------------------------
// W pre-pack (tf32-rounded): Bpk = {tf32(W[k0+l4][n]), tf32(W[k0+l4+4][n])}
// ---------------------------------------------------------------------------
__global__ void k_splitw(const float* __restrict__ W0, const float* __restrict__ W1) {
    int i = blockIdx.x * blockDim.x + threadIdx.x;
    if (i >= 16384) return;
    const float* W = (i < 8192) ? W0 : W1;
    int j  = i & 8191;
    int l4 = j & 3;
    int n  = (j >> 2) & 127;
    int ks = (j >> 9) & 3;
    int kc = j >> 11;
    int k0 = kc * 32 + ks * 8;
    g_Bpk[i] = make_float2(__uint_as_float(f2tf(W[(k0 + l4) * 128 + n])),
                           __uint_as_float(f2tf(W[(k0 + l4 + 4) * 128 + n])));
}

// ---------------------------------------------------------------------------
// CSR build
// ---------------------------------------------------------------------------
__global__ void k_zero_cnt() {
    int i = blockIdx.x * blockDim.x + threadIdx.x;
    if (i < 2 * N_NODES) g_cnt[i] = 0;
}

__global__ void k_count2(const int* __restrict__ dst1, const int* __restrict__ dst2) {
    int i = blockIdx.x * blockDim.x + threadIdx.x;
    int stride = gridDim.x * blockDim.x;
    for (; i < 2 * N_EDGES; i += stride) {
        if (i < N_EDGES) atomicAdd(&g_cnt[__ldg(dst1 + i)], 1);
        else             atomicAdd(&g_cnt[N_NODES + __ldg(dst2 + i - N_EDGES)], 1);
    }
}

__global__ __launch_bounds__(TILE)
void k_blocksum() {
    int g  = blockIdx.x / TILES_PER_G;
    int lt = blockIdx.x % TILES_PER_G;
    int li = lt * TILE + threadIdx.x;
    int c = (li < N_NODES) ? g_cnt[g * N_NODES + li] : 0;

    int lane = threadIdx.x & 31, w = threadIdx.x >> 5;
    for (int o = 16; o > 0; o >>= 1) c += __shfl_down_sync(~0u, c, o);
    __shared__ int ws[TILE / 32];
    if (lane == 0) ws[w] = c;
    __syncthreads();
    if (threadIdx.x == 0) {
        int s = 0;
#pragma unroll
        for (int i = 0; i < TILE / 32; i++) s += ws[i];
        g_tilesum[blockIdx.x] = s;
    }
}

__global__ __launch_bounds__(256)
void k_scanbase() {
    __shared__ int s[N_TILES];
    if (threadIdx.x < N_TILES) s[threadIdx.x] = g_tilesum[threadIdx.x];
    __syncthreads();
    if (threadIdx.x < 2) {
        int g = threadIdx.x;
        int run = 0;
        for (int t = 0; t < TILES_PER_G; t++) {
            g_tilebase[g * TILES_PER_G + t] = run;
            run += s[g * TILES_PER_G + t];
        }
        g_offs[g * (N_NODES + 1) + N_NODES] = run;
    }
}

__global__ __launch_bounds__(TILE)
void k_offsets() {
    int g  = blockIdx.x / TILES_PER_G;
    int lt = blockIdx.x % TILES_PER_G;
    int li = lt * TILE + threadIdx.x;
    int c = (li < N_NODES) ? g_cnt[g * N_NODES + li] : 0;

    int lane = threadIdx.x & 31, w = threadIdx.x >> 5;
    int v = c;
#pragma unroll
    for (int o = 1; o < 32; o <<= 1) {
        int t = __shfl_up_sync(~0u, v, o);
        if (lane >= o) v += t;
    }
    __shared__ int ws[TILE / 32];
    if (lane == 31) ws[w] = v;
    __syncthreads();
    if (w == 0 && lane < TILE / 32) {
        int s = ws[lane];
#pragma unroll
        for (int o = 1; o < TILE / 32; o <<= 1) {
            int t = __shfl_up_sync(0xffff, s, o);
            if (lane >= o) s += t;
        }
        ws[lane] = s;
    }
    __syncthreads();
    int excl = v - c + (w > 0 ? ws[w - 1] : 0);

    if (li < N_NODES) {
        int off = g_tilebase[blockIdx.x] + excl;
        g_offs[g * (N_NODES + 1) + li] = off;
        g_cur [g * N_NODES + li] = off;
        g_dinv[g * N_NODES + li] = rsqrtf(1.0f + (float)c);
    }
}

__global__ void k_fill2(const int* __restrict__ src1, const int* __restrict__ dst1,
                        const int* __restrict__ src2, const int* __restrict__ dst2) {
    int i = blockIdx.x * blockDim.x + threadIdx.x;
    int stride = gridDim.x * blockDim.x;
    for (; i < 2 * N_EDGES; i += stride) {
        if (i < N_EDGES) {
            int d = __ldg(dst1 + i);
            int p = atomicAdd(&g_cur[d], 1);
            g_csr[p] = __ldg(src1 + i);
        } else {
            int e = i - N_EDGES;
            int d = __ldg(dst2 + e);
            int p = atomicAdd(&g_cur[N_NODES + d], 1);
            g_csr[N_EDGES + p] = __ldg(src2 + e);
        }
    }
}

// ---------------------------------------------------------------------------
// GEMM (2-term TF32 split; hi/lo conversion hoisted to smem-fill time).
// hs[m][:] = x[m][:] @ W  (unscaled; dinv applied in aggregate). fp16 output.
// __launch_bounds__(256, 2): cap regs at 128 -> 2 CTAs/SM -> 16 warps/SM.
// smem: xhi 16KB + xlo 16KB + B 16KB = 48KB -> 96KB for 2 CTAs (fits).
// ---------------------------------------------------------------------------
__global__ __launch_bounds__(256, 2)
void k_gemm_tf32(const float* __restrict__ xA, const float* __restrict__ xB,
                 const float2* __restrict__ Bpk,
                 __half* __restrict__ hsA, __half* __restrict__ hsB) {
    __shared__ unsigned xhi[128 * 32];  // [m][c'*4+l4], c' = c ^ (m&7), tf32 hi
    __shared__ unsigned xlo[128 * 32];  // tf32 residual
    __shared__ float2 Bs[2048];         // [ks][n][l4] = {hi(k), hi(k+4)}

    const int tid  = threadIdx.x;
    const int lane = tid & 31;
    const int wid  = tid >> 5;
    const int g    = lane >> 2;
    const int l4   = lane & 3;
    const int wm   = (wid & 3) * 32;
    const int wn   = (wid >> 2) * 64;

    const int gph  = (blockIdx.x >= NBLK) ? 1 : 0;
    const int m0   = (blockIdx.x - gph * NBLK) * GM;
    const float* x = gph ? xB : xA;
    __half* hs     = gph ? hsB : hsA;

    float c[2][8][4];
#pragma unroll
    for (int mf = 0; mf < 2; mf++)
#pragma unroll
        for (int nb = 0; nb < 8; nb++)
#pragma unroll
            for (int q = 0; q < 4; q++) c[mf][nb][q] = 0.0f;

    for (int kc = 0; kc < 4; kc++) {
#pragma unroll
        for (int j = 0; j < 8; j++)
            Bs[tid + j * 256] = __ldg(Bpk + kc * 2048 + tid + j * 256);
#pragma unroll
        for (int i = 0; i < 4; i++) {
            int f = i * 256 + tid;
            int r = f >> 3, cc = f & 7;
            int R = m0 + r;
            float4 v = make_float4(0.f, 0.f, 0.f, 0.f);
            if (R < N_NODES)
                v = __ldg((const float4*)x + (size_t)R * 32 + kc * 8 + cc);
            // split to tf32 hi/lo at fill time (once), not in the MMA loop
            unsigned h0 = f2tf(v.x), h1 = f2tf(v.y), h2 = f2tf(v.z), h3 = f2tf(v.w);
            unsigned q0 = f2tf(v.x - __uint_as_float(h0));
            unsigned q1 = f2tf(v.y - __uint_as_float(h1));
            unsigned q2 = f2tf(v.z - __uint_as_float(h2));
            unsigned q3 = f2tf(v.w - __uint_as_float(h3));
            int idx = (r * 8 + (cc ^ (r & 7))) * 4;
            *(uint4*)&xhi[idx] = make_uint4(h0, h1, h2, h3);
            *(uint4*)&xlo[idx] = make_uint4(q0, q1, q2, q3);
        }
        __syncthreads();

#pragma unroll
        for (int ks = 0; ks < 4; ks++) {
            unsigned ahi[2][4], alo[2][4];
#pragma unroll
            for (int mf = 0; mf < 2; mf++) {
                int r0 = wm + mf * 16 + g;
                int r1 = r0 + 8;
                int i00 = (r0 * 8 + ((2 * ks)     ^ g)) * 4 + l4;  // k = l4
                int i01 = (r0 * 8 + ((2 * ks + 1) ^ g)) * 4 + l4;  // k = l4+4
                int i10 = (r1 * 8 + ((2 * ks)     ^ g)) * 4 + l4;
                int i11 = (r1 * 8 + ((2 * ks + 1) ^ g)) * 4 + l4;
                ahi[mf][0] = xhi[i00]; alo[mf][0] = xlo[i00];
                ahi[mf][1] = xhi[i10]; alo[mf][1] = xlo[i10];
                ahi[mf][2] = xhi[i01]; alo[mf][2] = xlo[i01];
                ahi[mf][3] = xhi[i11]; alo[mf][3] = xlo[i11];
            }
#pragma unroll
            for (int nb = 0; nb < 8; nb++) {
                uint2 b = *(const uint2*)&Bs[ks * 512 + (wn + nb * 8 + g) * 4 + l4];
#pragma unroll
                for (int mf = 0; mf < 2; mf++) {
                    mma8(c[mf][nb], ahi[mf], b.x, b.y);   // xhi * W
                    mma8(c[mf][nb], alo[mf], b.x, b.y);   // xlo * W
                }
            }
        }
        __syncthreads();
    }

    // Epilogue: store fp16 (no scaling)
#pragma unroll
    for (int mf = 0; mf < 2; mf++) {
        int R0 = m0 + wm + mf * 16 + g;
        int R1 = R0 + 8;
#pragma unroll
        for (int nb = 0; nb < 8; nb++) {
            int col = wn + nb * 8 + 2 * l4;
            if (R0 < N_NODES) {
                __half2 o = __floats2half2_rn(c[mf][nb][0], c[mf][nb][1]);
                *(__half2*)(hs + (size_t)R0 * 128 + col) = o;
            }
            if (R1 < N_NODES) {
                __half2 o = __floats2half2_rn(c[mf][nb][2], c[mf][nb][3]);
                *(__half2*)(hs + (size_t)R1 * 128 + col) = o;
            }
        }
    }
}

// ---------------------------------------------------------------------------
// Aggregate + finalize (fused, batched): one warp per dst node, lane = 4-dim
// chunk. 8 independent accumulator chains (MLP=8).
// out[n] = dinv[n]*( sum_e h[src_e]*dinv[src_e] + dinv[n]*h[n] ) + b  (+ ReLU)
// ---------------------------------------------------------------------------
__device__ __forceinline__ float4 h4tof4(uint2 v) {
    float2 lo = __half22float2(*(const __half2*)&v.x);
    float2 hi = __half22float2(*(const __half2*)&v.y);
    return make_float4(lo.x, lo.y, hi.x, hi.y);
}
__device__ __forceinline__ float4 f4add(float4 a, float4 b) {
    return make_float4(a.x + b.x, a.y + b.y, a.z + b.z, a.w + b.w);
}
__device__ __forceinline__ void f4fma(float4& a, float4 v, float s) {
    a.x = fmaf(v.x, s, a.x);
    a.y = fmaf(v.y, s, a.y);
    a.z = fmaf(v.z, s, a.z);
    a.w = fmaf(v.w, s, a.w);
}

__global__ __launch_bounds__(256)
void k_aggregate(const __half* __restrict__ hsA, const __half* __restrict__ hsB,
                 const float* __restrict__ b,
                 float* __restrict__ outA, float* __restrict__ outB, int do_relu) {
    int gnode = blockIdx.x * (blockDim.x >> 5) + (threadIdx.x >> 5);
    if (gnode >= 2 * N_NODES) return;
    int gph  = (gnode >= N_NODES) ? 1 : 0;
    int node = gnode - gph * N_NODES;
    int lane = threadIdx.x & 31;

    const int*   offs = g_offs + gph * (N_NODES + 1);
    const int*   csr  = g_csr  + gph * N_EDGES;
    const float* dinv = g_dinv + gph * N_NODES;
    const uint2* hs2  = (const uint2*)(gph ? hsB : hsA);
    float* out = gph ? outB : outA;

    int beg = __ldg(offs + node);
    int end = __ldg(offs + node + 1);
    float dd = __ldg(dinv + node);

    float4 a0 = make_float4(0.f, 0.f, 0.f, 0.f);
    float4 a1 = a0, a2 = a0, a3 = a0, a4 = a0, a5 = a0, a6 = a0, a7 = a0;
    f4fma(a0, h4tof4(__ldg(hs2 + (size_t)node * 32 + lane)), dd);  // self loop

    int e = beg;
    for (; e + 8 <= end; e += 8) {
        int s0 = __ldg(csr + e);     int s1 = __ldg(csr + e + 1);
        int s2 = __ldg(csr + e + 2); int s3 = __ldg(csr + e + 3);
        int s4 = __ldg(csr + e + 4); int s5 = __ldg(csr + e + 5);
        int s6 = __ldg(csr + e + 6); int s7 = __ldg(csr + e + 7);
        uint2 v0 = __ldg(hs2 + (size_t)s0 * 32 + lane);
        uint2 v1 = __ldg(hs2 + (size_t)s1 * 32 + lane);
        uint2 v2 = __ldg(hs2 + (size_t)s2 * 32 + lane);
        uint2 v3 = __ldg(hs2 + (size_t)s3 * 32 + lane);
        uint2 v4 = __ldg(hs2 + (size_t)s4 * 32 + lane);
        uint2 v5 = __ldg(hs2 + (size_t)s5 * 32 + lane);
        uint2 v6 = __ldg(hs2 + (size_t)s6 * 32 + lane);
        uint2 v7 = __ldg(hs2 + (size_t)s7 * 32 + lane);
        float d0 = __ldg(dinv + s0), d1 = __ldg(dinv + s1);
        float d2 = __ldg(dinv + s2), d3 = __ldg(dinv + s3);
        float d4 = __ldg(dinv + s4), d5 = __ldg(dinv + s5);
        float d6 = __ldg(dinv + s6), d7 = __ldg(dinv + s7);
        f4fma(a0, h4tof4(v0), d0);  f4fma(a1, h4tof4(v1), d1);
        f4fma(a2, h4tof4(v2), d2);  f4fma(a3, h4tof4(v3), d3);
        f4fma(a4, h4tof4(v4), d4);  f4fma(a5, h4tof4(v5), d5);
        f4fma(a6, h4tof4(v6), d6);  f4fma(a7, h4tof4(v7), d7);
    }
    for (; e + 2 <= end; e += 2) {
        int s0 = __ldg(csr + e), s1 = __ldg(csr + e + 1);
        uint2 v0 = __ldg(hs2 + (size_t)s0 * 32 + lane);
        uint2 v1 = __ldg(hs2 + (size_t)s1 * 32 + lane);
        float d0 = __ldg(dinv + s0), d1 = __ldg(dinv + s1);
        f4fma(a0, h4tof4(v0), d0);
        f4fma(a1, h4tof4(v1), d1);
    }
    if (e < end) {
        int s = __ldg(csr + e);
        f4fma(a0, h4tof4(__ldg(hs2 + (size_t)s * 32 + lane)), __ldg(dinv + s));
    }
    float4 acc = f4add(f4add(f4add(a0, a1), f4add(a2, a3)),
                       f4add(f4add(a4, a5), f4add(a6, a7)));

    float4 bb = __ldg(((const float4*)b) + lane);
    float4 o;
    o.x = fmaf(acc.x, dd, bb.x);
    o.y = fmaf(acc.y, dd, bb.y);
    o.z = fmaf(acc.z, dd, bb.z);
    o.w = fmaf(acc.w, dd, bb.w);
    if (do_relu) {
        o.x = fmaxf(o.x, 0.f); o.y = fmaxf(o.y, 0.f);
        o.z = fmaxf(o.z, 0.f); o.w = fmaxf(o.w, 0.f);
    }
    ((float4*)out)[(size_t)node * 32 + lane] = o;
}

// ---------------------------------------------------------------------------
// Launch. k_gemm_tf32 (layer 1) stays at launch index 3 for the ncu window.
// ---------------------------------------------------------------------------
extern "C" void kernel_launch(void* const* d_in, const int* in_sizes, int n_in,
                              void* d_out, int out_size) {
    const float* x1  = (const float*)d_in[0];
    const int*   ei1 = (const int*)  d_in[1];
    const float* x2  = (const float*)d_in[2];
    const int*   ei2 = (const int*)  d_in[3];
    const float* W0  = (const float*)d_in[4];
    const float* b0  = (const float*)d_in[5];
    const float* W1  = (const float*)d_in[6];
    const float* b1  = (const float*)d_in[7];
    float* out = (float*)d_out;

    const int* src1 = ei1;
    const int* dst1 = ei1 + N_EDGES;
    const int* src2 = ei2;
    const int* dst2 = ei2 + N_EDGES;

    float *h1, *h2;
    __half *hsA, *hsB;
    float2* Bpk;
    cudaGetSymbolAddress((void**)&hsA, g_hsA);
    cudaGetSymbolAddress((void**)&hsB, g_hsB);
    cudaGetSymbolAddress((void**)&h1,  g_h1);
    cudaGetSymbolAddress((void**)&h2,  g_h2);
    cudaGetSymbolAddress((void**)&Bpk, g_Bpk);

    k_splitw<<<64, 256>>>(W0, W1);                         // 0
    k_zero_cnt<<<(2 * N_NODES + 255) / 256, 256>>>();      // 1
    k_count2<<<2048, 256>>>(dst1, dst2);                   // 2
    k_gemm_tf32<<<2 * NBLK, 256>>>(x1, x2, Bpk, hsA, hsB); // 3  (ncu window)
    k_blocksum<<<N_TILES, TILE>>>();                       // 4
    k_scanbase<<<1, 256>>>();                              // 5
    k_offsets<<<N_TILES, TILE>>>();                        // 6
    k_fill2<<<2048, 256>>>(src1, dst1, src2, dst2);        // 7

    const int AGG_GRID = (2 * N_NODES * 32 + 255) / 256;

    k_aggregate<<<AGG_GRID, 256>>>(hsA, hsB, b0, h1, h2, 1);
    k_gemm_tf32<<<2 * NBLK, 256>>>(h1, h2, Bpk + 8192, hsA, hsB);
    k_aggregate<<<AGG_GRID, 256>>>(hsA, hsB, b1, out, out + (size_t)N_NODES * DIM, 0);
}

// round 11
// speedup vs baseline: 2.1909x; 1.1018x over previous
#include <cuda_runtime.h>
#include <cuda_fp16.h>
#include <cuda_bf16.h>

#define N_NODES 50000
#define DIM     128
#define N_EDGES 800000
#define TILE    512
#define TILES_PER_G 98          // ceil(50000/512)
#define N_TILES (2 * TILES_PER_G)
#define GM      128             // GEMM block M
#define NBLK    ((N_NODES + GM - 1) / GM)   // 391

// ---------------------------------------------------------------------------
// Scratch (device globals — no allocation allowed in kernel_launch)
// ---------------------------------------------------------------------------
__device__ int    g_cnt [2 * N_NODES];
__device__ int    g_offs[2 * (N_NODES + 1)];
__device__ int    g_cur [2 * N_NODES];
__device__ int    g_csr [2 * N_EDGES];
__device__ float  g_dinv[2 * N_NODES];
__device__ __half g_hsA [N_NODES * DIM];     // x @ W  (unscaled, fp16), graph 1
__device__ __half g_hsB [N_NODES * DIM];     // graph 2
__device__ float  g_h1  [N_NODES * DIM];     // hidden activations graph 1
__device__ float  g_h2  [N_NODES * DIM];     // graph 2
__device__ int    g_tilesum [N_TILES];
__device__ int    g_tilebase[N_TILES];
__device__ float2 g_Bpk[2 * 8192];   // tf32(W0/W1), fragment-packed:
                                     // [layer][kc(4)][ks(4)][n(128)][l4(4)] = {hi(k), hi(k+4)}

// ---------------------------------------------------------------------------
// tf32 helpers
// ---------------------------------------------------------------------------
__device__ __forceinline__ unsigned f2tf(float f) {
    unsigned r;
    asm("cvt.rna.tf32.f32 %0, %1;" : "=r"(r) : "f"(f));
    return r;
}

__device__ __forceinline__ void mma8(float c[4], const unsigned a[4],
                                     unsigned b0, unsigned b1) {
    asm volatile(
        "mma.sync.aligned.m16n8k8.row.col.f32.tf32.tf32.f32 "
        "{%0,%1,%2,%3}, {%4,%5,%6,%7}, {%8,%9}, {%0,%1,%2,%3};"
        : "+f"(c[0]), "+f"(c[1]), "+f"(c[2]), "+f"(c[3])
        : "r"(a[0]), "r"(a[1]), "r"(a[2]), "r"(a[3]), "r"(b0), "r"(b1));
}

// ---------------------------------------------------------------------------
// W pre-pack (tf32-rounded): Bpk = {tf32(W[k0+l4][n]), tf32(W[k0+l4+4][n])}
// ---------------------------------------------------------------------------
__global__ void k_splitw(const float* __restrict__ W0, const float* __restrict__ W1) {
    int i = blockIdx.x * blockDim.x + threadIdx.x;
    if (i >= 16384) return;
    const float* W = (i < 8192) ? W0 : W1;
    int j  = i & 8191;
    int l4 = j & 3;
    int n  = (j >> 2) & 127;
    int ks = (j >> 9) & 3;
    int kc = j >> 11;
    int k0 = kc * 32 + ks * 8;
    g_Bpk[i] = make_float2(__uint_as_float(f2tf(W[(k0 + l4) * 128 + n])),
                           __uint_as_float(f2tf(W[(k0 + l4 + 4) * 128 + n])));
}

// ---------------------------------------------------------------------------
// CSR build
// ---------------------------------------------------------------------------
__global__ void k_zero_cnt() {
    int i = blockIdx.x * blockDim.x + threadIdx.x;
    if (i < 2 * N_NODES) g_cnt[i] = 0;
}

__global__ void k_count2(const int* __restrict__ dst1, const int* __restrict__ dst2) {
    int i = blockIdx.x * blockDim.x + threadIdx.x;
    int stride = gridDim.x * blockDim.x;
    for (; i < 2 * N_EDGES; i += stride) {
        if (i < N_EDGES) atomicAdd(&g_cnt[__ldg(dst1 + i)], 1);
        else             atomicAdd(&g_cnt[N_NODES + __ldg(dst2 + i - N_EDGES)], 1);
    }
}

__global__ __launch_bounds__(TILE)
void k_blocksum() {
    int g  = blockIdx.x / TILES_PER_G;
    int lt = blockIdx.x % TILES_PER_G;
    int li = lt * TILE + threadIdx.x;
    int c = (li < N_NODES) ? g_cnt[g * N_NODES + li] : 0;

    int lane = threadIdx.x & 31, w = threadIdx.x >> 5;
    for (int o = 16; o > 0; o >>= 1) c += __shfl_down_sync(~0u, c, o);
    __shared__ int ws[TILE / 32];
    if (lane == 0) ws[w] = c;
    __syncthreads();
    if (threadIdx.x == 0) {
        int s = 0;
#pragma unroll
        for (int i = 0; i < TILE / 32; i++) s += ws[i];
        g_tilesum[blockIdx.x] = s;
    }
}

__global__ __launch_bounds__(256)
void k_scanbase() {
    __shared__ int s[N_TILES];
    if (threadIdx.x < N_TILES) s[threadIdx.x] = g_tilesum[threadIdx.x];
    __syncthreads();
    if (threadIdx.x < 2) {
        int g = threadIdx.x;
        int run = 0;
        for (int t = 0; t < TILES_PER_G; t++) {
            g_tilebase[g * TILES_PER_G + t] = run;
            run += s[g * TILES_PER_G + t];
        }
        g_offs[g * (N_NODES + 1) + N_NODES] = run;
    }
}

__global__ __launch_bounds__(TILE)
void k_offsets() {
    int g  = blockIdx.x / TILES_PER_G;
    int lt = blockIdx.x % TILES_PER_G;
    int li = lt * TILE + threadIdx.x;
    int c = (li < N_NODES) ? g_cnt[g * N_NODES + li] : 0;

    int lane = threadIdx.x & 31, w = threadIdx.x >> 5;
    int v = c;
#pragma unroll
    for (int o = 1; o < 32; o <<= 1) {
        int t = __shfl_up_sync(~0u, v, o);
        if (lane >= o) v += t;
    }
    __shared__ int ws[TILE / 32];
    if (lane == 31) ws[w] = v;
    __syncthreads();
    if (w == 0 && lane < TILE / 32) {
        int s = ws[lane];
#pragma unroll
        for (int o = 1; o < TILE / 32; o <<= 1) {
            int t = __shfl_up_sync(0xffff, s, o);
            if (lane >= o) s += t;
        }
        ws[lane] = s;
    }
    __syncthreads();
    int excl = v - c + (w > 0 ? ws[w - 1] : 0);

    if (li < N_NODES) {
        int off = g_tilebase[blockIdx.x] + excl;
        g_offs[g * (N_NODES + 1) + li] = off;
        g_cur [g * N_NODES + li] = off;
        g_dinv[g * N_NODES + li] = rsqrtf(1.0f + (float)c);
    }
}

__global__ void k_fill2(const int* __restrict__ src1, const int* __restrict__ dst1,
                        const int* __restrict__ src2, const int* __restrict__ dst2) {
    int i = blockIdx.x * blockDim.x + threadIdx.x;
    int stride = gridDim.x * blockDim.x;
    for (; i < 2 * N_EDGES; i += stride) {
        if (i < N_EDGES) {
            int d = __ldg(dst1 + i);
            int p = atomicAdd(&g_cur[d], 1);
            g_csr[p] = __ldg(src1 + i);
        } else {
            int e = i - N_EDGES;
            int d = __ldg(dst2 + e);
            int p = atomicAdd(&g_cur[N_NODES + d], 1);
            g_csr[N_EDGES + p] = __ldg(src2 + e);
        }
    }
}

// ---------------------------------------------------------------------------
// GEMM (single-pass TF32, fragment-native A layout in smem).
// hs[m][:] = x[m][:] @ W  (unscaled; dinv applied in aggregate). fp16 output.
//
// A smem layout: xs[(mb*4 + ks)*32 + lane_rot][slot], slot = {a0,a1,a2,a3}
// where mb = 16-row block (0..7), ks = k-octet (0..3), lane_rot =
// (lane + ks*2) & 31 (rotation spreads fill-store banks). Mainloop A load =
// ONE conflict-free LDS.128 per (mf, ks). B layout unchanged (LDS.64).
// smem: A 16KB + B 16KB = 32KB.
// ---------------------------------------------------------------------------
__global__ __launch_bounds__(256, 2)
void k_gemm_tf32(const float* __restrict__ xA, const float* __restrict__ xB,
                 const float2* __restrict__ Bpk,
                 __half* __restrict__ hsA, __half* __restrict__ hsB) {
    __shared__ uint4  xs[8 * 4 * 32];   // [(mb*4+ks)*32 + lane_rot] = {a0,a1,a2,a3}
    __shared__ float2 Bs[2048];         // [ks][n][l4] = {hi(k), hi(k+4)}

    const int tid  = threadIdx.x;
    const int lane = tid & 31;
    const int wid  = tid >> 5;
    const int g    = lane >> 2;
    const int l4   = lane & 3;
    const int wm   = (wid & 3) * 32;
    const int wn   = (wid >> 2) * 64;

    const int gph  = (blockIdx.x >= NBLK) ? 1 : 0;
    const int m0   = (blockIdx.x - gph * NBLK) * GM;
    const float* x = gph ? xB : xA;
    __half* hs     = gph ? hsB : hsA;

    float c[2][8][4];
#pragma unroll
    for (int mf = 0; mf < 2; mf++)
#pragma unroll
        for (int nb = 0; nb < 8; nb++)
#pragma unroll
            for (int q = 0; q < 4; q++) c[mf][nb][q] = 0.0f;

    for (int kc = 0; kc < 4; kc++) {
#pragma unroll
        for (int j = 0; j < 8; j++)
            Bs[tid + j * 256] = __ldg(Bpk + kc * 2048 + tid + j * 256);

        // Fill A in fragment-native layout (tf32-convert once, at fill time)
        unsigned* xsu = (unsigned*)xs;
#pragma unroll
        for (int i = 0; i < 4; i++) {
            int f  = i * 256 + tid;
            int r  = f >> 3;           // row in tile (0..127)
            int cc = f & 7;            // float4 column (k = cc*4 + j)
            int R  = m0 + r;
            float4 v = make_float4(0.f, 0.f, 0.f, 0.f);
            if (R < N_NODES)
                v = __ldg((const float4*)x + (size_t)R * 32 + kc * 8 + cc);
            int rr   = r & 15;
            int mb   = r >> 4;                    // 16-row block (0..7)
            int g2   = rr & 7;
            int slot = (rr >> 3) + (cc & 1) * 2;  // a0/a1/a2/a3
            int ks   = cc >> 1;
            int base = (mb * 4 + ks) * 32;
            unsigned t0 = f2tf(v.x), t1 = f2tf(v.y), t2 = f2tf(v.z), t3 = f2tf(v.w);
            xsu[((base + ((g2 * 4 + 0 + ks * 2) & 31)) << 2) + slot] = t0;
            xsu[((base + ((g2 * 4 + 1 + ks * 2) & 31)) << 2) + slot] = t1;
            xsu[((base + ((g2 * 4 + 2 + ks * 2) & 31)) << 2) + slot] = t2;
            xsu[((base + ((g2 * 4 + 3 + ks * 2) & 31)) << 2) + slot] = t3;
        }
        __syncthreads();

#pragma unroll
        for (int ks = 0; ks < 4; ks++) {
            unsigned afrag[2][4];
#pragma unroll
            for (int mf = 0; mf < 2; mf++) {
                int mb = (wid & 3) * 2 + mf;
                uint4 a = xs[(mb * 4 + ks) * 32 + ((lane + ks * 2) & 31)];
                afrag[mf][0] = a.x; afrag[mf][1] = a.y;
                afrag[mf][2] = a.z; afrag[mf][3] = a.w;
            }
#pragma unroll
            for (int nb = 0; nb < 8; nb++) {
                uint2 b = *(const uint2*)&Bs[ks * 512 + (wn + nb * 8 + g) * 4 + l4];
#pragma unroll
                for (int mf = 0; mf < 2; mf++)
                    mma8(c[mf][nb], afrag[mf], b.x, b.y);
            }
        }
        __syncthreads();
    }

    // Epilogue: store fp16 (no scaling)
#pragma unroll
    for (int mf = 0; mf < 2; mf++) {
        int R0 = m0 + wm + mf * 16 + g;
        int R1 = R0 + 8;
#pragma unroll
        for (int nb = 0; nb < 8; nb++) {
            int col = wn + nb * 8 + 2 * l4;
            if (R0 < N_NODES) {
                __half2 o = __floats2half2_rn(c[mf][nb][0], c[mf][nb][1]);
                *(__half2*)(hs + (size_t)R0 * 128 + col) = o;
            }
            if (R1 < N_NODES) {
                __half2 o = __floats2half2_rn(c[mf][nb][2], c[mf][nb][3]);
                *(__half2*)(hs + (size_t)R1 * 128 + col) = o;
            }
        }
    }
}

// ---------------------------------------------------------------------------
// Aggregate + finalize (fused, batched): one warp per dst node, lane = 4-dim
// chunk. 8 independent accumulator chains (MLP=8).
// out[n] = dinv[n]*( sum_e h[src_e]*dinv[src_e] + dinv[n]*h[n] ) + b  (+ ReLU)
// ---------------------------------------------------------------------------
__device__ __forceinline__ float4 h4tof4(uint2 v) {
    float2 lo = __half22float2(*(const __half2*)&v.x);
    float2 hi = __half22float2(*(const __half2*)&v.y);
    return make_float4(lo.x, lo.y, hi.x, hi.y);
}
__device__ __forceinline__ float4 f4add(float4 a, float4 b) {
    return make_float4(a.x + b.x, a.y + b.y, a.z + b.z, a.w + b.w);
}
__device__ __forceinline__ void f4fma(float4& a, float4 v, float s) {
    a.x = fmaf(v.x, s, a.x);
    a.y = fmaf(v.y, s, a.y);
    a.z = fmaf(v.z, s, a.z);
    a.w = fmaf(v.w, s, a.w);
}

__global__ __launch_bounds__(256)
void k_aggregate(const __half* __restrict__ hsA, const __half* __restrict__ hsB,
                 const float* __restrict__ b,
                 float* __restrict__ outA, float* __restrict__ outB, int do_relu) {
    int gnode = blockIdx.x * (blockDim.x >> 5) + (threadIdx.x >> 5);
    if (gnode >= 2 * N_NODES) return;
    int gph  = (gnode >= N_NODES) ? 1 : 0;
    int node = gnode - gph * N_NODES;
    int lane = threadIdx.x & 31;

    const int*   offs = g_offs + gph * (N_NODES + 1);
    const int*   csr  = g_csr  + gph * N_EDGES;
    const float* dinv = g_dinv + gph * N_NODES;
    const uint2* hs2  = (const uint2*)(gph ? hsB : hsA);
    float* out = gph ? outB : outA;

    int beg = __ldg(offs + node);
    int end = __ldg(offs + node + 1);
    float dd = __ldg(dinv + node);

    float4 a0 = make_float4(0.f, 0.f, 0.f, 0.f);
    float4 a1 = a0, a2 = a0, a3 = a0, a4 = a0, a5 = a0, a6 = a0, a7 = a0;
    f4fma(a0, h4tof4(__ldg(hs2 + (size_t)node * 32 + lane)), dd);  // self loop

    int e = beg;
    for (; e + 8 <= end; e += 8) {
        int s0 = __ldg(csr + e);     int s1 = __ldg(csr + e + 1);
        int s2 = __ldg(csr + e + 2); int s3 = __ldg(csr + e + 3);
        int s4 = __ldg(csr + e + 4); int s5 = __ldg(csr + e + 5);
        int s6 = __ldg(csr + e + 6); int s7 = __ldg(csr + e + 7);
        uint2 v0 = __ldg(hs2 + (size_t)s0 * 32 + lane);
        uint2 v1 = __ldg(hs2 + (size_t)s1 * 32 + lane);
        uint2 v2 = __ldg(hs2 + (size_t)s2 * 32 + lane);
        uint2 v3 = __ldg(hs2 + (size_t)s3 * 32 + lane);
        uint2 v4 = __ldg(hs2 + (size_t)s4 * 32 + lane);
        uint2 v5 = __ldg(hs2 + (size_t)s5 * 32 + lane);
        uint2 v6 = __ldg(hs2 + (size_t)s6 * 32 + lane);
        uint2 v7 = __ldg(hs2 + (size_t)s7 * 32 + lane);
        float d0 = __ldg(dinv + s0), d1 = __ldg(dinv + s1);
        float d2 = __ldg(dinv + s2), d3 = __ldg(dinv + s3);
        float d4 = __ldg(dinv + s4), d5 = __ldg(dinv + s5);
        float d6 = __ldg(dinv + s6), d7 = __ldg(dinv + s7);
        f4fma(a0, h4tof4(v0), d0);  f4fma(a1, h4tof4(v1), d1);
        f4fma(a2, h4tof4(v2), d2);  f4fma(a3, h4tof4(v3), d3);
        f4fma(a4, h4tof4(v4), d4);  f4fma(a5, h4tof4(v5), d5);
        f4fma(a6, h4tof4(v6), d6);  f4fma(a7, h4tof4(v7), d7);
    }
    for (; e + 2 <= end; e += 2) {
        int s0 = __ldg(csr + e), s1 = __ldg(csr + e + 1);
        uint2 v0 = __ldg(hs2 + (size_t)s0 * 32 + lane);
        uint2 v1 = __ldg(hs2 + (size_t)s1 * 32 + lane);
        float d0 = __ldg(dinv + s0), d1 = __ldg(dinv + s1);
        f4fma(a0, h4tof4(v0), d0);
        f4fma(a1, h4tof4(v1), d1);
    }
    if (e < end) {
        int s = __ldg(csr + e);
        f4fma(a0, h4tof4(__ldg(hs2 + (size_t)s * 32 + lane)), __ldg(dinv + s));
    }
    float4 acc = f4add(f4add(f4add(a0, a1), f4add(a2, a3)),
                       f4add(f4add(a4, a5), f4add(a6, a7)));

    float4 bb = __ldg(((const float4*)b) + lane);
    float4 o;
    o.x = fmaf(acc.x, dd, bb.x);
    o.y = fmaf(acc.y, dd, bb.y);
    o.z = fmaf(acc.z, dd, bb.z);
    o.w = fmaf(acc.w, dd, bb.w);
    if (do_relu) {
        o.x = fmaxf(o.x, 0.f); o.y = fmaxf(o.y, 0.f);
        o.z = fmaxf(o.z, 0.f); o.w = fmaxf(o.w, 0.f);
    }
    ((float4*)out)[(size_t)node * 32 + lane] = o;
}

// ---------------------------------------------------------------------------
// Launch. k_gemm_tf32 (layer 1) stays at launch index 3 for the ncu window.
// ---------------------------------------------------------------------------
extern "C" void kernel_launch(void* const* d_in, const int* in_sizes, int n_in,
                              void* d_out, int out_size) {
    const float* x1  = (const float*)d_in[0];
    const int*   ei1 = (const int*)  d_in[1];
    const float* x2  = (const float*)d_in[2];
    const int*   ei2 = (const int*)  d_in[3];
    const float* W0  = (const float*)d_in[4];
    const float* b0  = (const float*)d_in[5];
    const float* W1  = (const float*)d_in[6];
    const float* b1  = (const float*)d_in[7];
    float* out = (float*)d_out;

    const int* src1 = ei1;
    const int* dst1 = ei1 + N_EDGES;
    const int* src2 = ei2;
    const int* dst2 = ei2 + N_EDGES;

    float *h1, *h2;
    __half *hsA, *hsB;
    float2* Bpk;
    cudaGetSymbolAddress((void**)&hsA, g_hsA);
    cudaGetSymbolAddress((void**)&hsB, g_hsB);
    cudaGetSymbolAddress((void**)&h1,  g_h1);
    cudaGetSymbolAddress((void**)&h2,  g_h2);
    cudaGetSymbolAddress((void**)&Bpk, g_Bpk);

    k_splitw<<<64, 256>>>(W0, W1);                         // 0
    k_zero_cnt<<<(2 * N_NODES + 255) / 256, 256>>>();      // 1
    k_count2<<<2048, 256>>>(dst1, dst2);                   // 2
    k_gemm_tf32<<<2 * NBLK, 256>>>(x1, x2, Bpk, hsA, hsB); // 3  (ncu window)
    k_blocksum<<<N_TILES, TILE>>>();                       // 4
    k_scanbase<<<1, 256>>>();                              // 5
    k_offsets<<<N_TILES, TILE>>>();                        // 6
    k_fill2<<<2048, 256>>>(src1, dst1, src2, dst2);        // 7

    const int AGG_GRID = (2 * N_NODES * 32 + 255) / 256;

    k_aggregate<<<AGG_GRID, 256>>>(hsA, hsB, b0, h1, h2, 1);
    k_gemm_tf32<<<2 * NBLK, 256>>>(h1, h2, Bpk + 8192, hsA, hsB);
    k_aggregate<<<AGG_GRID, 256>>>(hsA, hsB, b1, out, out + (size_t)N_NODES * DIM, 0);
}